// round 4
// baseline (speedup 1.0000x reference)
#include <cuda_runtime.h>
#include <cuda_bf16.h>
#include <mma.h>
#include <stdint.h>

using namespace nvcuda;

constexpr int N     = 8192;
constexpr int WORDS = N / 32;

// ---------------------------------------------------------------------------
// Scratch
// ---------------------------------------------------------------------------
__device__ uint32_t       g_bits[(size_t)N * WORDS];   // 8 MB adjacency bitmask
__device__ float          g_dinv[N];
__device__ float          g_ydf[(size_t)N * 128];      // dinv_j * (Y@W) fp32 [row][col]
__device__ __nv_bfloat16  g_ydh[(size_t)N * 128];      // hi split [row][col]
__device__ __nv_bfloat16  g_ydl[(size_t)N * 128];      // lo split [row][col]
__device__ float          g_h[(size_t)N * 64];
__device__ float          g_rexd[(size_t)N * 128];     // [re | xd]
__device__ __nv_bfloat16  g_reh[(size_t)N * 64];
__device__ __nv_bfloat16  g_rel[(size_t)N * 64];

// ---------------------------------------------------------------------------
// cp.async helpers
// ---------------------------------------------------------------------------
__device__ __forceinline__ void cp16(void* smem_dst, const void* gsrc) {
    uint32_t d = (uint32_t)__cvta_generic_to_shared(smem_dst);
    asm volatile("cp.async.cg.shared.global [%0], [%1], 16;\n" :: "r"(d), "l"(gsrc));
}
__device__ __forceinline__ void cp_commit() {
    asm volatile("cp.async.commit_group;\n" ::: "memory");
}
__device__ __forceinline__ void cp_wait0() {
    asm volatile("cp.async.wait_group 0;\n" ::: "memory");
}
__device__ __forceinline__ uint32_t pack2bf(float a, float b) {
    __nv_bfloat162 t = __floats2bfloat162_rn(a, b);
    return *(uint32_t*)&t;
}

// ---------------------------------------------------------------------------
// 1) Prep: bitmask + dinv
// ---------------------------------------------------------------------------
__global__ void __launch_bounds__(256) prep_kernel(const int* __restrict__ edge) {
    int row  = blockIdx.x;
    int lane = threadIdx.x & 31;
    int warp = threadIdx.x >> 5;
    __shared__ int wcnt[8];

    const int* erow = edge + (size_t)row * N;
    int cnt = 0;
#pragma unroll 4
    for (int w = 0; w < 32; ++w) {
        int col = warp * 1024 + w * 32 + lane;
        unsigned mask = __ballot_sync(0xFFFFFFFFu, erow[col] != 0);
        if (lane == 0) {
            g_bits[(size_t)row * WORDS + warp * 32 + w] = mask;
            cnt += __popc(mask);
        }
    }
    if (lane == 0) wcnt[warp] = cnt;
    __syncthreads();
    if (threadIdx.x == 0) {
        int deg = 1;
#pragma unroll
        for (int i = 0; i < 8; ++i) deg += wcnt[i];
        g_dinv[row] = rsqrtf((float)deg);
    }
}

// ---------------------------------------------------------------------------
// 2) small GEMM v4: yd = dinv_r * (act @ W) -> ydf + hi/lo
//    Each thread owns 4 consecutive cols: LDS.128 W + broadcast act, 2-way k ILP.
// ---------------------------------------------------------------------------
template <int KIN, int COUT>
__global__ void __launch_bounds__(256) small_gemm4(const float* __restrict__ act_ext,
                                                   int act_sel, int act_ld, int act_c0,
                                                   const float* __restrict__ W,
                                                   int out_ld, int out_c0) {
    const float* act = (act_sel == 1) ? g_h : ((act_sel == 2) ? g_rexd : act_ext);
    __shared__ float sW[KIN * COUT];      // <= 8192 floats
    __shared__ float sact[16 * KIN];

    int tid = threadIdx.x;
    for (int i = tid; i < KIN * COUT; i += 256) sW[i] = W[i];

    int rbase = blockIdx.x * 16;
    for (int j = tid; j < 16 * KIN; j += 256) {
        int r = j / KIN, k = j - r * KIN;
        sact[j] = act[(size_t)(rbase + r) * act_ld + act_c0 + k];
    }
    __syncthreads();

    constexpr int TPR = COUT / 4;         // threads per row
    constexpr int RPI = 256 / TPR;        // rows per iteration

    int c4 = (tid % TPR) * 4;
    int ry0 = tid / TPR;

#pragma unroll
    for (int it = 0; it < 16; it += RPI) {
        int ry = it + ry0;
        const float* sa = &sact[ry * KIN];
        float4 a0 = make_float4(0.f, 0.f, 0.f, 0.f);
        float4 a1 = make_float4(0.f, 0.f, 0.f, 0.f);
#pragma unroll
        for (int k = 0; k < KIN; k += 2) {
            float v0 = sa[k], v1 = sa[k + 1];
            float4 w0 = *(const float4*)&sW[k * COUT + c4];
            float4 w1 = *(const float4*)&sW[(k + 1) * COUT + c4];
            a0.x = fmaf(v0, w0.x, a0.x); a0.y = fmaf(v0, w0.y, a0.y);
            a0.z = fmaf(v0, w0.z, a0.z); a0.w = fmaf(v0, w0.w, a0.w);
            a1.x = fmaf(v1, w1.x, a1.x); a1.y = fmaf(v1, w1.y, a1.y);
            a1.z = fmaf(v1, w1.z, a1.z); a1.w = fmaf(v1, w1.w, a1.w);
        }
        int row = rbase + ry;
        float di = g_dinv[row];
        float4 y;
        y.x = di * (a0.x + a1.x); y.y = di * (a0.y + a1.y);
        y.z = di * (a0.z + a1.z); y.w = di * (a0.w + a1.w);

        size_t o = (size_t)row * out_ld + out_c0 + c4;
        *(float4*)&g_ydf[o] = y;

        float hx = __bfloat162float(__float2bfloat16(y.x));
        float hy = __bfloat162float(__float2bfloat16(y.y));
        float hz = __bfloat162float(__float2bfloat16(y.z));
        float hw = __bfloat162float(__float2bfloat16(y.w));
        uint2 hp = make_uint2(pack2bf(hx, hy), pack2bf(hz, hw));
        uint2 lp = make_uint2(pack2bf(y.x - hx, y.y - hy), pack2bf(y.z - hz, y.w - hw));
        *(uint2*)&g_ydh[o] = hp;
        *(uint2*)&g_ydl[o] = lp;
    }
}

// ---------------------------------------------------------------------------
// 3) big adjacency GEMM v4: out = lrelu(dinv_i*(B@yd + yd_i) + bias)
//    BM x 64 tile, KC=64 double-buffered cp.async, bitmask A expansion.
// ---------------------------------------------------------------------------
template <int BM>
__global__ void __launch_bounds__(256) big_gcn4(const float* __restrict__ bias_a,
                                                const float* __restrict__ bias_b,
                                                int bsplit, int PW,
                                                float* out_ext, int dest_sel,
                                                int out_ld, int cb0) {
    constexpr int KC   = 64;
    constexpr int NC   = N / KC;           // 128 chunks
    constexpr int LDA  = 72;               // elems (144 B rows, LDSM conflict-free)
    constexpr int LDB  = 72;
    constexpr int ASZ  = BM * LDA;         // bf16 elems per A buf
    constexpr int BSZ  = KC * LDB;         // bf16 elems per B buf (h or l)
    constexpr int WM   = BM / 4;           // warp rows (4x2 warp grid)
    constexpr int FM   = WM / 16;
    constexpr int THB  = 256 / BM;         // threads per A row
    constexpr int BITS = KC / THB;         // bits expanded per thread

    extern __shared__ __align__(16) __nv_bfloat16 smem[];
    __nv_bfloat16* sA  = smem;                       // [2][ASZ]
    __nv_bfloat16* sBh = smem + 2 * ASZ;             // [2][BSZ]
    __nv_bfloat16* sBl = smem + 2 * ASZ + 2 * BSZ;   // [2][BSZ]

    float* out = (dest_sel == 0) ? g_h : ((dest_sel == 1) ? g_rexd : out_ext);

    int tid  = threadIdx.x;
    int warp = tid >> 5;
    int wr   = warp >> 1;
    int wc   = warp & 1;
    int r0   = blockIdx.x * BM;
    int c0   = cb0 + blockIdx.y * 64;

    // A expansion mapping
    int arow = tid / THB;
    int bpos = (tid % THB) * BITS;

    wmma::fragment<wmma::accumulator, 16, 16, 16, float> acc[FM][2];
#pragma unroll
    for (int fm = 0; fm < FM; ++fm)
#pragma unroll
        for (int fn = 0; fn < 2; ++fn) wmma::fill_fragment(acc[fm][fn], 0.f);

    auto fetchB = [&](int ch, int buf) {
        int k0 = ch * KC;
#pragma unroll
        for (int s = tid; s < 512; s += 256) {
            int row = s >> 3, seg = s & 7;
            size_t g = (size_t)(k0 + row) * PW + c0 + seg * 8;
            cp16(&sBh[buf * BSZ + row * LDB + seg * 8], &g_ydh[g]);
            cp16(&sBl[buf * BSZ + row * LDB + seg * 8], &g_ydl[g]);
        }
        cp_commit();
    };
    auto expandA = [&](int ch, int buf) {
        uint32_t word = g_bits[(size_t)(r0 + arow) * WORDS + ch * 2 + (bpos >> 5)];
        uint32_t w = word >> (bpos & 31);
#pragma unroll
        for (int j = 0; j < BITS / 8; ++j) {
            uint32_t bb = w >> (j * 8);
            uint4 u;
            u.x = ((bb & 1u)  ? 0x3F80u : 0u) | ((bb & 2u)   ? 0x3F800000u : 0u);
            u.y = ((bb & 4u)  ? 0x3F80u : 0u) | ((bb & 8u)   ? 0x3F800000u : 0u);
            u.z = ((bb & 16u) ? 0x3F80u : 0u) | ((bb & 32u)  ? 0x3F800000u : 0u);
            u.w = ((bb & 64u) ? 0x3F80u : 0u) | ((bb & 128u) ? 0x3F800000u : 0u);
            *(uint4*)&sA[buf * ASZ + arow * LDA + bpos + j * 8] = u;
        }
    };

    fetchB(0, 0);
    expandA(0, 0);
    cp_wait0();
    __syncthreads();

    int buf = 0;
    for (int ch = 0; ch < NC; ++ch) {
        int nbuf = buf ^ 1;
        if (ch + 1 < NC) {
            fetchB(ch + 1, nbuf);
            expandA(ch + 1, nbuf);
        }
#pragma unroll
        for (int ks = 0; ks < 4; ++ks) {
            wmma::fragment<wmma::matrix_a, 16, 16, 16, __nv_bfloat16, wmma::row_major> a[FM];
#pragma unroll
            for (int fm = 0; fm < FM; ++fm)
                wmma::load_matrix_sync(a[fm],
                    &sA[buf * ASZ + (wr * WM + fm * 16) * LDA + ks * 16], LDA);
#pragma unroll
            for (int fn = 0; fn < 2; ++fn) {
                wmma::fragment<wmma::matrix_b, 16, 16, 16, __nv_bfloat16, wmma::row_major> bh, bl;
                int bcol = wc * 32 + fn * 16;
                wmma::load_matrix_sync(bh, &sBh[buf * BSZ + (ks * 16) * LDB + bcol], LDB);
                wmma::load_matrix_sync(bl, &sBl[buf * BSZ + (ks * 16) * LDB + bcol], LDB);
#pragma unroll
                for (int fm = 0; fm < FM; ++fm) {
                    wmma::mma_sync(acc[fm][fn], a[fm], bh, acc[fm][fn]);
                    wmma::mma_sync(acc[fm][fn], a[fm], bl, acc[fm][fn]);
                }
            }
        }
        if (ch + 1 < NC) cp_wait0();
        __syncthreads();
        buf = nbuf;
    }

    // epilogue via SMEM roundtrip (aliases buffers)
    float* sC = (float*)smem;
#pragma unroll
    for (int fm = 0; fm < FM; ++fm)
#pragma unroll
        for (int fn = 0; fn < 2; ++fn)
            wmma::store_matrix_sync(&sC[(wr * WM + fm * 16) * 64 + wc * 32 + fn * 16],
                                    acc[fm][fn], 64, wmma::mem_row_major);
    __syncthreads();

    bool left = (c0 < bsplit);
    const float* bias = left ? bias_a : bias_b;
    int boff = left ? c0 : c0 - bsplit;

    for (int idx = tid; idx < BM * 16; idx += 256) {
        int r  = idx >> 4;
        int c4 = (idx & 15) * 4;
        int gr = r0 + r;
        float di = g_dinv[gr];
        float4 s = *(float4*)&sC[r * 64 + c4];
        float4 yd = *(const float4*)&g_ydf[(size_t)gr * PW + c0 + c4];
        float4 o;
        o.x = di * (s.x + yd.x) + bias[boff + c4 + 0];
        o.y = di * (s.y + yd.y) + bias[boff + c4 + 1];
        o.z = di * (s.z + yd.z) + bias[boff + c4 + 2];
        o.w = di * (s.w + yd.w) + bias[boff + c4 + 3];
        o.x = (o.x > 0.f) ? o.x : 0.01f * o.x;
        o.y = (o.y > 0.f) ? o.y : 0.01f * o.y;
        o.z = (o.z > 0.f) ? o.z : 0.01f * o.z;
        o.w = (o.w > 0.f) ? o.w : 0.01f * o.w;
        *(float4*)&out[(size_t)gr * out_ld + c0 + c4] = o;
    }
}

constexpr int SMEM_BG128 = (2 * 128 * 72 + 4 * 64 * 72) * 2;  // 73728 B
constexpr int SMEM_BG64  = (2 * 64 * 72 + 4 * 64 * 72) * 2;   // 55296 B

// ---------------------------------------------------------------------------
// 4) split re into hi/lo
// ---------------------------------------------------------------------------
__global__ void split_re_kernel() {
    int i = blockIdx.x * blockDim.x + threadIdx.x;
    int r = i >> 6, c = i & 63;
    float v = g_rexd[r * 128 + c];
    __nv_bfloat16 hi = __float2bfloat16(v);
    g_reh[i] = hi;
    g_rel[i] = __float2bfloat16(v - __bfloat162float(hi));
}

// ---------------------------------------------------------------------------
// 5) recon = sigmoid(re @ re^T), symmetric (upper triangle, write both)
// ---------------------------------------------------------------------------
__device__ __forceinline__ float fsig(float x) {
    return __fdividef(1.f, 1.f + __expf(-x));
}

__global__ void __launch_bounds__(256) recon_kernel(float* __restrict__ out) {
    if (blockIdx.x < blockIdx.y) return;

    constexpr int LD  = 72;
    constexpr int LDC = 68;
    __shared__ alignas(32) __nv_bfloat16 smem[4 * 64 * LD];
    __nv_bfloat16* sAh = smem;
    __nv_bfloat16* sAl = smem + 1 * 64 * LD;
    __nv_bfloat16* sBh = smem + 2 * 64 * LD;
    __nv_bfloat16* sBl = smem + 3 * 64 * LD;

    int tid = threadIdx.x;
    int r0 = blockIdx.y * 64, c0 = blockIdx.x * 64;

    int lr = tid >> 2, lc = (tid & 3) << 4;
    {
        const uint4* sh = (const uint4*)&g_reh[(size_t)(r0 + lr) * 64 + lc];
        const uint4* sl = (const uint4*)&g_rel[(size_t)(r0 + lr) * 64 + lc];
        uint4* dh = (uint4*)&sAh[lr * LD + lc];
        uint4* dl = (uint4*)&sAl[lr * LD + lc];
        dh[0] = sh[0]; dh[1] = sh[1];
        dl[0] = sl[0]; dl[1] = sl[1];
        const uint4* th = (const uint4*)&g_reh[(size_t)(c0 + lr) * 64 + lc];
        const uint4* tl = (const uint4*)&g_rel[(size_t)(c0 + lr) * 64 + lc];
        uint4* eh = (uint4*)&sBh[lr * LD + lc];
        uint4* el = (uint4*)&sBl[lr * LD + lc];
        eh[0] = th[0]; eh[1] = th[1];
        el[0] = tl[0]; el[1] = tl[1];
    }
    __syncthreads();

    int warp = tid >> 5;
    int wr = warp >> 1, wc = warp & 1;

    wmma::fragment<wmma::accumulator, 16, 16, 16, float> acc[2];
    wmma::fill_fragment(acc[0], 0.f);
    wmma::fill_fragment(acc[1], 0.f);

#pragma unroll
    for (int kc = 0; kc < 4; ++kc) {
        int k = kc * 16;
        wmma::fragment<wmma::matrix_a, 16, 16, 16, __nv_bfloat16, wmma::row_major> ah, al;
        wmma::load_matrix_sync(ah, &sAh[(wr * 16) * LD + k], LD);
        wmma::load_matrix_sync(al, &sAl[(wr * 16) * LD + k], LD);
#pragma unroll
        for (int j = 0; j < 2; ++j) {
            int col = wc * 32 + j * 16;
            wmma::fragment<wmma::matrix_b, 16, 16, 16, __nv_bfloat16, wmma::col_major> bh, bl;
            wmma::load_matrix_sync(bh, &sBh[col * LD + k], LD);
            wmma::load_matrix_sync(bl, &sBl[col * LD + k], LD);
            wmma::mma_sync(acc[j], ah, bh, acc[j]);
            wmma::mma_sync(acc[j], ah, bl, acc[j]);
            wmma::mma_sync(acc[j], al, bh, acc[j]);
        }
    }
    __syncthreads();

    float* sC = reinterpret_cast<float*>(smem);
#pragma unroll
    for (int j = 0; j < 2; ++j)
        wmma::store_matrix_sync(&sC[(wr * 16) * LDC + wc * 32 + j * 16], acc[j], LDC,
                                wmma::mem_row_major);
    __syncthreads();

#pragma unroll
    for (int it = 0; it < 4; ++it) {
        int f4 = tid + it * 256;
        int r  = f4 >> 4;
        int c4 = (f4 & 15) << 2;
        float4 o;
        o.x = fsig(sC[r * LDC + c4 + 0]);
        o.y = fsig(sC[r * LDC + c4 + 1]);
        o.z = fsig(sC[r * LDC + c4 + 2]);
        o.w = fsig(sC[r * LDC + c4 + 3]);
        *(float4*)&out[(size_t)(r0 + r) * N + c0 + c4] = o;
    }
    if (blockIdx.x != blockIdx.y) {
#pragma unroll
        for (int it = 0; it < 4; ++it) {
            int f4 = tid + it * 256;
            int r  = f4 >> 4;
            int c4 = (f4 & 15) << 2;
            float4 o;
            o.x = fsig(sC[(c4 + 0) * LDC + r]);
            o.y = fsig(sC[(c4 + 1) * LDC + r]);
            o.z = fsig(sC[(c4 + 2) * LDC + r]);
            o.w = fsig(sC[(c4 + 3) * LDC + r]);
            *(float4*)&out[(size_t)(c0 + r) * N + r0 + c4] = o;
        }
    }
}

// ---------------------------------------------------------------------------
// Launch chain.  Layer-2 big_gcn split into two launches so ncu (-s 5 -c 1)
// profiles a big_gcn at launch #6.
// ---------------------------------------------------------------------------
extern "C" void kernel_launch(void* const* d_in, const int* in_sizes, int n_in,
                              void* d_out, int out_size) {
    (void)in_sizes; (void)n_in; (void)out_size;
    const float* x    = (const float*)d_in[0];
    const int*   edge = (const int*)  d_in[1];
    const float* W1   = (const float*)d_in[2];
    const float* b1   = (const float*)d_in[3];
    const float* W2   = (const float*)d_in[4];
    const float* b2   = (const float*)d_in[5];
    const float* We   = (const float*)d_in[6];
    const float* be   = (const float*)d_in[7];
    const float* Wd1  = (const float*)d_in[8];
    const float* bd1  = (const float*)d_in[9];
    const float* Wd2  = (const float*)d_in[10];
    const float* bd2  = (const float*)d_in[11];

    float* out   = (float*)d_out;
    float* recon = out;
    float* xout  = out + (size_t)N * N;
    float* zout  = xout + (size_t)N * 128;

    cudaFuncSetAttribute(big_gcn4<128>, cudaFuncAttributeMaxDynamicSharedMemorySize, SMEM_BG128);
    cudaFuncSetAttribute(big_gcn4<64>,  cudaFuncAttributeMaxDynamicSharedMemorySize, SMEM_BG64);

    // 1
    prep_kernel<<<N, 256>>>(edge);

    // layer 1: h = lrelu(nadj @ (x@W1) + b1)   [N,64]
    small_gemm4<128, 64><<<512, 256>>>(x, 0, 128, 0, W1, 64, 0);                      // 2
    big_gcn4<64><<<dim3(128, 1), 256, SMEM_BG64>>>(b1, b1, 64, 64, nullptr, 0, 64, 0); // 3

    // layer 2: z = lrelu(nadj @ (h@W2) + b2)   [N,128]  (split: cols 0-63, 64-127)
    small_gemm4<64, 128><<<512, 256>>>(nullptr, 1, 64, 0, W2, 128, 0);                // 4
    big_gcn4<128><<<dim3(64, 1), 256, SMEM_BG128>>>(b2, b2, 128, 128, zout, 2, 128, 0);   // 5
    big_gcn4<128><<<dim3(64, 1), 256, SMEM_BG128>>>(b2, b2, 128, 128, zout, 2, 128, 64);  // 6 <- profiled

    // layers 3+4 fused: [re | xd]
    small_gemm4<128, 64><<<512, 256>>>(zout, 0, 128, 0, We, 128, 0);                  // 7
    small_gemm4<128, 64><<<512, 256>>>(zout, 0, 128, 0, Wd1, 128, 64);                // 8
    big_gcn4<128><<<dim3(64, 2), 256, SMEM_BG128>>>(be, bd1, 64, 128, nullptr, 1, 128, 0); // 9

    split_re_kernel<<<(N * 64) / 256, 256>>>();                                      // 10

    // layer 5: x_out = lrelu(nadj @ (xd@Wd2) + bd2)  [N,128]
    small_gemm4<64, 128><<<512, 256>>>(nullptr, 2, 128, 64, Wd2, 128, 0);             // 11
    big_gcn4<128><<<dim3(64, 2), 256, SMEM_BG128>>>(bd2, bd2, 128, 128, xout, 2, 128, 0); // 12

    // recon = sigmoid(re @ re^T)
    recon_kernel<<<dim3(128, 128), 256>>>(recon);                                     // 13
}

// round 5
// speedup vs baseline: 1.3239x; 1.3239x over previous
#include <cuda_runtime.h>
#include <cuda_bf16.h>
#include <mma.h>
#include <stdint.h>

using namespace nvcuda;

constexpr int N     = 8192;
constexpr int WORDS = N / 32;

// ---------------------------------------------------------------------------
// Scratch
// ---------------------------------------------------------------------------
__device__ uint32_t       g_bits[(size_t)N * WORDS];   // 8 MB adjacency bitmask
__device__ float          g_dinv[N];
__device__ float          g_ydf[(size_t)N * 128];      // dinv_j * (Y@W) fp32 [row][col]
__device__ __nv_bfloat16  g_ydh[(size_t)N * 128];      // hi split
__device__ __nv_bfloat16  g_ydl[(size_t)N * 128];      // lo split
__device__ float          g_part[2 * (size_t)N * 128]; // split-K partials (fp32)
__device__ float          g_h[(size_t)N * 64];
__device__ float          g_rexd[(size_t)N * 128];     // [re | xd]
__device__ __nv_bfloat16  g_reh[(size_t)N * 64];
__device__ __nv_bfloat16  g_rel[(size_t)N * 64];

// ---------------------------------------------------------------------------
// cp.async helpers
// ---------------------------------------------------------------------------
__device__ __forceinline__ void cp16(void* smem_dst, const void* gsrc) {
    uint32_t d = (uint32_t)__cvta_generic_to_shared(smem_dst);
    asm volatile("cp.async.cg.shared.global [%0], [%1], 16;\n" :: "r"(d), "l"(gsrc));
}
__device__ __forceinline__ void cp_commit() {
    asm volatile("cp.async.commit_group;\n" ::: "memory");
}
__device__ __forceinline__ void cp_wait0() {
    asm volatile("cp.async.wait_group 0;\n" ::: "memory");
}
__device__ __forceinline__ uint32_t pack2bf(float a, float b) {
    __nv_bfloat162 t = __floats2bfloat162_rn(a, b);
    return *(uint32_t*)&t;
}

// ---------------------------------------------------------------------------
// 1) Prep: bitmask + dinv
// ---------------------------------------------------------------------------
__global__ void __launch_bounds__(256) prep_kernel(const int* __restrict__ edge) {
    int row  = blockIdx.x;
    int lane = threadIdx.x & 31;
    int warp = threadIdx.x >> 5;
    __shared__ int wcnt[8];

    const int* erow = edge + (size_t)row * N;
    int cnt = 0;
#pragma unroll 4
    for (int w = 0; w < 32; ++w) {
        int col = warp * 1024 + w * 32 + lane;
        unsigned mask = __ballot_sync(0xFFFFFFFFu, erow[col] != 0);
        if (lane == 0) {
            g_bits[(size_t)row * WORDS + warp * 32 + w] = mask;
            cnt += __popc(mask);
        }
    }
    if (lane == 0) wcnt[warp] = cnt;
    __syncthreads();
    if (threadIdx.x == 0) {
        int deg = 1;
#pragma unroll
        for (int i = 0; i < 8; ++i) deg += wcnt[i];
        g_dinv[row] = rsqrtf((float)deg);
    }
}

// ---------------------------------------------------------------------------
// spacer/utility: zero partial buffers (also aligns profiler to position 4)
// ---------------------------------------------------------------------------
__global__ void zero_part_kernel() {
    size_t i = (size_t)blockIdx.x * blockDim.x + threadIdx.x;
    *(float4*)&g_part[i * 4] = make_float4(0.f, 0.f, 0.f, 0.f);
}

// ---------------------------------------------------------------------------
// 2) small GEMM: yd = dinv_r * (act @ W) -> ydf + hi/lo.  Optional dual weights.
// ---------------------------------------------------------------------------
template <int KIN, int COUT>
__global__ void __launch_bounds__(256) small_gemm5(const float* __restrict__ act_ext,
                                                   int act_sel, int act_ld, int act_c0,
                                                   const float* __restrict__ Wa,
                                                   const float* __restrict__ Wb,
                                                   int out_ld, int out_c0) {
    const float* act = (act_sel == 1) ? g_h : ((act_sel == 2) ? g_rexd : act_ext);
    __shared__ float sW[KIN * COUT];
    __shared__ float sact[16 * KIN];

    int tid = threadIdx.x;
    if (Wb == nullptr) {
        for (int i = tid; i < KIN * COUT; i += 256) sW[i] = Wa[i];
    } else {
        for (int i = tid; i < KIN * COUT; i += 256) {
            int k = i / COUT, c = i % COUT;
            sW[i] = (c < 64) ? Wa[k * 64 + c] : Wb[k * 64 + (c - 64)];
        }
    }

    int rbase = blockIdx.x * 16;
    for (int j = tid; j < 16 * KIN; j += 256) {
        int r = j / KIN, k = j - r * KIN;
        sact[j] = act[(size_t)(rbase + r) * act_ld + act_c0 + k];
    }
    __syncthreads();

    constexpr int TPR = COUT / 4;
    constexpr int RPI = 256 / TPR;

    int c4 = (tid % TPR) * 4;
    int ry0 = tid / TPR;

#pragma unroll
    for (int it = 0; it < 16; it += RPI) {
        int ry = it + ry0;
        const float* sa = &sact[ry * KIN];
        float4 a0 = make_float4(0.f, 0.f, 0.f, 0.f);
        float4 a1 = make_float4(0.f, 0.f, 0.f, 0.f);
#pragma unroll
        for (int k = 0; k < KIN; k += 2) {
            float v0 = sa[k], v1 = sa[k + 1];
            float4 w0 = *(const float4*)&sW[k * COUT + c4];
            float4 w1 = *(const float4*)&sW[(k + 1) * COUT + c4];
            a0.x = fmaf(v0, w0.x, a0.x); a0.y = fmaf(v0, w0.y, a0.y);
            a0.z = fmaf(v0, w0.z, a0.z); a0.w = fmaf(v0, w0.w, a0.w);
            a1.x = fmaf(v1, w1.x, a1.x); a1.y = fmaf(v1, w1.y, a1.y);
            a1.z = fmaf(v1, w1.z, a1.z); a1.w = fmaf(v1, w1.w, a1.w);
        }
        int row = rbase + ry;
        float di = g_dinv[row];
        float4 y;
        y.x = di * (a0.x + a1.x); y.y = di * (a0.y + a1.y);
        y.z = di * (a0.z + a1.z); y.w = di * (a0.w + a1.w);

        size_t o = (size_t)row * out_ld + out_c0 + c4;
        *(float4*)&g_ydf[o] = y;

        float hx = __bfloat162float(__float2bfloat16(y.x));
        float hy = __bfloat162float(__float2bfloat16(y.y));
        float hz = __bfloat162float(__float2bfloat16(y.z));
        float hw = __bfloat162float(__float2bfloat16(y.w));
        *(uint2*)&g_ydh[o] = make_uint2(pack2bf(hx, hy), pack2bf(hz, hw));
        *(uint2*)&g_ydl[o] = make_uint2(pack2bf(y.x - hx, y.y - hy), pack2bf(y.z - hz, y.w - hw));
    }
}

// ---------------------------------------------------------------------------
// 3) big adjacency GEMM v5 (split-K): partial[bz] = B[:, khalf] @ yd[khalf, :]
//    128x64 CTA tile, grid (rows, cols, 2).  Raw fp32 partials out.
// ---------------------------------------------------------------------------
constexpr int SMEM_BG = (2 * 128 * 72 + 4 * 64 * 72) * 2;  // 73728 B

__global__ void __launch_bounds__(256, 2) big_gcn5(int PW) {
    constexpr int BM  = 128;
    constexpr int KC  = 64;
    constexpr int NC2 = (N / 2) / KC;      // 64 chunks per K-half
    constexpr int LDA = 72;
    constexpr int LDB = 72;
    constexpr int ASZ = BM * LDA;
    constexpr int BSZ = KC * LDB;
    constexpr int WM  = 32;                // 4x2 warp grid, warp tile 32x32
    constexpr int FM  = 2;

    extern __shared__ __align__(16) __nv_bfloat16 smem[];
    __nv_bfloat16* sA  = smem;                       // [2][ASZ]
    __nv_bfloat16* sBh = smem + 2 * ASZ;             // [2][BSZ]
    __nv_bfloat16* sBl = smem + 2 * ASZ + 2 * BSZ;   // [2][BSZ]

    int tid  = threadIdx.x;
    int warp = tid >> 5;
    int wr   = warp >> 1;
    int wc   = warp & 1;
    int r0   = blockIdx.x * BM;
    int c0   = blockIdx.y * 64;
    int ks0  = blockIdx.z * (N / 2);

    // A expansion mapping: 2 threads per row, 32 bits each
    int arow = tid >> 1;
    int bpos = (tid & 1) * 32;
    size_t wbase = (size_t)(r0 + arow) * WORDS + (ks0 >> 5) + (bpos >> 5);

    wmma::fragment<wmma::accumulator, 16, 16, 16, float> acc[FM][2];
#pragma unroll
    for (int fm = 0; fm < FM; ++fm)
#pragma unroll
        for (int fn = 0; fn < 2; ++fn) wmma::fill_fragment(acc[fm][fn], 0.f);

    auto fetchB = [&](int ch, int buf) {
        int k0 = ks0 + ch * KC;
#pragma unroll
        for (int s = tid; s < 512; s += 256) {
            int row = s >> 3, seg = s & 7;
            size_t g = (size_t)(k0 + row) * PW + c0 + seg * 8;
            cp16(&sBh[buf * BSZ + row * LDB + seg * 8], &g_ydh[g]);
            cp16(&sBl[buf * BSZ + row * LDB + seg * 8], &g_ydl[g]);
        }
        cp_commit();
    };
    auto expandA = [&](int ch, int buf) {
        uint32_t w = g_bits[wbase + ch * 2];
#pragma unroll
        for (int j = 0; j < 4; ++j) {
            uint32_t bb = w >> (j * 8);
            uint4 u;
            u.x = ((bb & 1u)  ? 0x3F80u : 0u) | ((bb & 2u)   ? 0x3F800000u : 0u);
            u.y = ((bb & 4u)  ? 0x3F80u : 0u) | ((bb & 8u)   ? 0x3F800000u : 0u);
            u.z = ((bb & 16u) ? 0x3F80u : 0u) | ((bb & 32u)  ? 0x3F800000u : 0u);
            u.w = ((bb & 64u) ? 0x3F80u : 0u) | ((bb & 128u) ? 0x3F800000u : 0u);
            *(uint4*)&sA[buf * ASZ + arow * LDA + bpos + j * 8] = u;
        }
    };

    fetchB(0, 0);
    expandA(0, 0);
    cp_wait0();
    __syncthreads();

    int buf = 0;
    for (int ch = 0; ch < NC2; ++ch) {
        int nbuf = buf ^ 1;
        if (ch + 1 < NC2) {
            fetchB(ch + 1, nbuf);
            expandA(ch + 1, nbuf);
        }
#pragma unroll
        for (int ks = 0; ks < 4; ++ks) {
            wmma::fragment<wmma::matrix_a, 16, 16, 16, __nv_bfloat16, wmma::row_major> a[FM];
#pragma unroll
            for (int fm = 0; fm < FM; ++fm)
                wmma::load_matrix_sync(a[fm],
                    &sA[buf * ASZ + (wr * WM + fm * 16) * LDA + ks * 16], LDA);
#pragma unroll
            for (int fn = 0; fn < 2; ++fn) {
                wmma::fragment<wmma::matrix_b, 16, 16, 16, __nv_bfloat16, wmma::row_major> bh, bl;
                int bcol = wc * 32 + fn * 16;
                wmma::load_matrix_sync(bh, &sBh[buf * BSZ + (ks * 16) * LDB + bcol], LDB);
                wmma::load_matrix_sync(bl, &sBl[buf * BSZ + (ks * 16) * LDB + bcol], LDB);
#pragma unroll
                for (int fm = 0; fm < FM; ++fm) {
                    wmma::mma_sync(acc[fm][fn], a[fm], bh, acc[fm][fn]);
                    wmma::mma_sync(acc[fm][fn], a[fm], bl, acc[fm][fn]);
                }
            }
        }
        if (ch + 1 < NC2) cp_wait0();
        __syncthreads();
        buf = nbuf;
    }

    // raw fp32 partial straight from accumulators
    float* pout = &g_part[(size_t)blockIdx.z * N * PW];
#pragma unroll
    for (int fm = 0; fm < FM; ++fm)
#pragma unroll
        for (int fn = 0; fn < 2; ++fn)
            wmma::store_matrix_sync(
                &pout[(size_t)(r0 + wr * WM + fm * 16) * PW + c0 + wc * 32 + fn * 16],
                acc[fm][fn], PW, wmma::mem_row_major);
}

// ---------------------------------------------------------------------------
// 3b) combine: out = lrelu(dinv_i*(p0 + p1 + yd_i) + bias)
// ---------------------------------------------------------------------------
__global__ void __launch_bounds__(256) combine_kernel(const float* __restrict__ bias_a,
                                                      const float* __restrict__ bias_b,
                                                      int bsplit, int C,
                                                      float* out_ext, int dest_sel,
                                                      int out_ld) {
    float* out = (dest_sel == 0) ? g_h : ((dest_sel == 1) ? g_rexd : out_ext);
    int i = blockIdx.x * 256 + threadIdx.x;     // float4 index
    int cq = C >> 2;
    int row = i / cq;
    int c4  = (i - row * cq) * 4;
    float di = g_dinv[row];
    size_t o = (size_t)row * C + c4;
    float4 p0 = *(const float4*)&g_part[o];
    float4 p1 = *(const float4*)&g_part[(size_t)N * C + o];
    float4 yd = *(const float4*)&g_ydf[o];
    float4 v;
    const float* bias = (c4 < bsplit) ? bias_a : bias_b;
    int bo = (c4 < bsplit) ? c4 : c4 - bsplit;
    v.x = di * (p0.x + p1.x + yd.x) + bias[bo + 0];
    v.y = di * (p0.y + p1.y + yd.y) + bias[bo + 1];
    v.z = di * (p0.z + p1.z + yd.z) + bias[bo + 2];
    v.w = di * (p0.w + p1.w + yd.w) + bias[bo + 3];
    v.x = (v.x > 0.f) ? v.x : 0.01f * v.x;
    v.y = (v.y > 0.f) ? v.y : 0.01f * v.y;
    v.z = (v.z > 0.f) ? v.z : 0.01f * v.z;
    v.w = (v.w > 0.f) ? v.w : 0.01f * v.w;
    *(float4*)&out[(size_t)row * out_ld + c4] = v;
}

// ---------------------------------------------------------------------------
// 4) split re into hi/lo
// ---------------------------------------------------------------------------
__global__ void split_re_kernel() {
    int i = blockIdx.x * blockDim.x + threadIdx.x;
    int r = i >> 6, c = i & 63;
    float v = g_rexd[r * 128 + c];
    __nv_bfloat16 hi = __float2bfloat16(v);
    g_reh[i] = hi;
    g_rel[i] = __float2bfloat16(v - __bfloat162float(hi));
}

// ---------------------------------------------------------------------------
// 5) recon = sigmoid(re @ re^T), symmetric
// ---------------------------------------------------------------------------
__device__ __forceinline__ float fsig(float x) {
    return __fdividef(1.f, 1.f + __expf(-x));
}

__global__ void __launch_bounds__(256) recon_kernel(float* __restrict__ out) {
    if (blockIdx.x < blockIdx.y) return;

    constexpr int LD  = 72;
    constexpr int LDC = 68;
    __shared__ alignas(32) __nv_bfloat16 smem[4 * 64 * LD];
    __nv_bfloat16* sAh = smem;
    __nv_bfloat16* sAl = smem + 1 * 64 * LD;
    __nv_bfloat16* sBh = smem + 2 * 64 * LD;
    __nv_bfloat16* sBl = smem + 3 * 64 * LD;

    int tid = threadIdx.x;
    int r0 = blockIdx.y * 64, c0 = blockIdx.x * 64;

    int lr = tid >> 2, lc = (tid & 3) << 4;
    {
        const uint4* sh = (const uint4*)&g_reh[(size_t)(r0 + lr) * 64 + lc];
        const uint4* sl = (const uint4*)&g_rel[(size_t)(r0 + lr) * 64 + lc];
        uint4* dh = (uint4*)&sAh[lr * LD + lc];
        uint4* dl = (uint4*)&sAl[lr * LD + lc];
        dh[0] = sh[0]; dh[1] = sh[1];
        dl[0] = sl[0]; dl[1] = sl[1];
        const uint4* th = (const uint4*)&g_reh[(size_t)(c0 + lr) * 64 + lc];
        const uint4* tl = (const uint4*)&g_rel[(size_t)(c0 + lr) * 64 + lc];
        uint4* eh = (uint4*)&sBh[lr * LD + lc];
        uint4* el = (uint4*)&sBl[lr * LD + lc];
        eh[0] = th[0]; eh[1] = th[1];
        el[0] = tl[0]; el[1] = tl[1];
    }
    __syncthreads();

    int warp = tid >> 5;
    int wr = warp >> 1, wc = warp & 1;

    wmma::fragment<wmma::accumulator, 16, 16, 16, float> acc[2];
    wmma::fill_fragment(acc[0], 0.f);
    wmma::fill_fragment(acc[1], 0.f);

#pragma unroll
    for (int kc = 0; kc < 4; ++kc) {
        int k = kc * 16;
        wmma::fragment<wmma::matrix_a, 16, 16, 16, __nv_bfloat16, wmma::row_major> ah, al;
        wmma::load_matrix_sync(ah, &sAh[(wr * 16) * LD + k], LD);
        wmma::load_matrix_sync(al, &sAl[(wr * 16) * LD + k], LD);
#pragma unroll
        for (int j = 0; j < 2; ++j) {
            int col = wc * 32 + j * 16;
            wmma::fragment<wmma::matrix_b, 16, 16, 16, __nv_bfloat16, wmma::col_major> bh, bl;
            wmma::load_matrix_sync(bh, &sBh[col * LD + k], LD);
            wmma::load_matrix_sync(bl, &sBl[col * LD + k], LD);
            wmma::mma_sync(acc[j], ah, bh, acc[j]);
            wmma::mma_sync(acc[j], ah, bl, acc[j]);
            wmma::mma_sync(acc[j], al, bh, acc[j]);
        }
    }
    __syncthreads();

    float* sC = reinterpret_cast<float*>(smem);
#pragma unroll
    for (int j = 0; j < 2; ++j)
        wmma::store_matrix_sync(&sC[(wr * 16) * LDC + wc * 32 + j * 16], acc[j], LDC,
                                wmma::mem_row_major);
    __syncthreads();

#pragma unroll
    for (int it = 0; it < 4; ++it) {
        int f4 = tid + it * 256;
        int r  = f4 >> 4;
        int c4 = (f4 & 15) << 2;
        float4 o;
        o.x = fsig(sC[r * LDC + c4 + 0]);
        o.y = fsig(sC[r * LDC + c4 + 1]);
        o.z = fsig(sC[r * LDC + c4 + 2]);
        o.w = fsig(sC[r * LDC + c4 + 3]);
        *(float4*)&out[(size_t)(r0 + r) * N + c0 + c4] = o;
    }
    if (blockIdx.x != blockIdx.y) {
#pragma unroll
        for (int it = 0; it < 4; ++it) {
            int f4 = tid + it * 256;
            int r  = f4 >> 4;
            int c4 = (f4 & 15) << 2;
            float4 o;
            o.x = fsig(sC[(c4 + 0) * LDC + r]);
            o.y = fsig(sC[(c4 + 1) * LDC + r]);
            o.z = fsig(sC[(c4 + 2) * LDC + r]);
            o.w = fsig(sC[(c4 + 3) * LDC + r]);
            *(float4*)&out[(size_t)(c0 + r) * N + r0 + c4] = o;
        }
    }
}

// ---------------------------------------------------------------------------
// Launch chain (position 4 = big_gcn5 -> gets profiled)
// ---------------------------------------------------------------------------
extern "C" void kernel_launch(void* const* d_in, const int* in_sizes, int n_in,
                              void* d_out, int out_size) {
    (void)in_sizes; (void)n_in; (void)out_size;
    const float* x    = (const float*)d_in[0];
    const int*   edge = (const int*)  d_in[1];
    const float* W1   = (const float*)d_in[2];
    const float* b1   = (const float*)d_in[3];
    const float* W2   = (const float*)d_in[4];
    const float* b2   = (const float*)d_in[5];
    const float* We   = (const float*)d_in[6];
    const float* be   = (const float*)d_in[7];
    const float* Wd1  = (const float*)d_in[8];
    const float* bd1  = (const float*)d_in[9];
    const float* Wd2  = (const float*)d_in[10];
    const float* bd2  = (const float*)d_in[11];

    float* out   = (float*)d_out;
    float* recon = out;
    float* xout  = out + (size_t)N * N;
    float* zout  = xout + (size_t)N * 128;

    cudaFuncSetAttribute(big_gcn5, cudaFuncAttributeMaxDynamicSharedMemorySize, SMEM_BG);

    prep_kernel<<<N, 256>>>(edge);                                            // 1
    small_gemm5<128, 64><<<512, 256>>>(x, 0, 128, 0, W1, nullptr, 64, 0);     // 2
    zero_part_kernel<<<2048, 256>>>();                                        // 3 (spacer)

    // layer 1: h = lrelu(nadj @ (x@W1) + b1)   [N,64]
    big_gcn5<<<dim3(64, 1, 2), 256, SMEM_BG>>>(64);                           // 4 <- profiled
    combine_kernel<<<N * 64 / 1024, 256>>>(b1, b1, 64, 64, nullptr, 0, 64);   // 5

    // layer 2: z = lrelu(nadj @ (h@W2) + b2)   [N,128]
    small_gemm5<64, 128><<<512, 256>>>(nullptr, 1, 64, 0, W2, nullptr, 128, 0);   // 6
    big_gcn5<<<dim3(64, 2, 2), 256, SMEM_BG>>>(128);                              // 7
    combine_kernel<<<N * 128 / 1024, 256>>>(b2, b2, 128, 128, zout, 2, 128);      // 8

    // layers 3+4 fused: [re | xd] = lrelu(nadj @ (z@[We|Wd1]) + [be|bd1])
    small_gemm5<128, 128><<<512, 256>>>(zout, 0, 128, 0, We, Wd1, 128, 0);        // 9
    big_gcn5<<<dim3(64, 2, 2), 256, SMEM_BG>>>(128);                              // 10
    combine_kernel<<<N * 128 / 1024, 256>>>(be, bd1, 64, 128, nullptr, 1, 128);   // 11

    split_re_kernel<<<(N * 64) / 256, 256>>>();                                   // 12

    // layer 5: x_out = lrelu(nadj @ (xd@Wd2) + bd2)  [N,128]
    small_gemm5<64, 128><<<512, 256>>>(nullptr, 2, 128, 64, Wd2, nullptr, 128, 0); // 13
    big_gcn5<<<dim3(64, 2, 2), 256, SMEM_BG>>>(128);                               // 14
    combine_kernel<<<N * 128 / 1024, 256>>>(bd2, bd2, 128, 128, xout, 2, 128);     // 15

    // recon = sigmoid(re @ re^T)
    recon_kernel<<<dim3(128, 128), 256>>>(recon);                                  // 16
}

// round 6
// speedup vs baseline: 1.3961x; 1.0545x over previous
#include <cuda_runtime.h>
#include <cuda_bf16.h>
#include <mma.h>
#include <stdint.h>

using namespace nvcuda;

constexpr int N     = 8192;
constexpr int WORDS = N / 32;

// ---------------------------------------------------------------------------
// Scratch
// ---------------------------------------------------------------------------
__device__ uint32_t       g_bits[(size_t)N * WORDS];   // 8 MB adjacency bitmask
__device__ float          g_dinv[N];
__device__ float          g_ydf[(size_t)N * 128];      // dinv_j * (Y@W) fp32 [row][col]
__device__ __nv_bfloat16  g_ydh[(size_t)N * 128];      // hi split
__device__ __nv_bfloat16  g_ydl[(size_t)N * 128];      // lo split
__device__ float          g_part[4 * (size_t)N * 64 > 2 * (size_t)N * 128
                                 ? 4 * (size_t)N * 64 : 2 * (size_t)N * 128];
__device__ float          g_h[(size_t)N * 64];
__device__ float          g_rexd[(size_t)N * 128];     // [re | xd]
__device__ __nv_bfloat16  g_reh[(size_t)N * 64];
__device__ __nv_bfloat16  g_rel[(size_t)N * 64];

// ---------------------------------------------------------------------------
// cp.async helpers
// ---------------------------------------------------------------------------
__device__ __forceinline__ void cp16(void* smem_dst, const void* gsrc) {
    uint32_t d = (uint32_t)__cvta_generic_to_shared(smem_dst);
    asm volatile("cp.async.cg.shared.global [%0], [%1], 16;\n" :: "r"(d), "l"(gsrc));
}
__device__ __forceinline__ void cp_commit() {
    asm volatile("cp.async.commit_group;\n" ::: "memory");
}
__device__ __forceinline__ void cp_wait0() {
    asm volatile("cp.async.wait_group 0;\n" ::: "memory");
}
__device__ __forceinline__ uint32_t pack2bf(float a, float b) {
    __nv_bfloat162 t = __floats2bfloat162_rn(a, b);
    return *(uint32_t*)&t;
}

// ---------------------------------------------------------------------------
// 1) Prep: bitmask + dinv
// ---------------------------------------------------------------------------
__global__ void __launch_bounds__(256) prep_kernel(const int* __restrict__ edge) {
    int row  = blockIdx.x;
    int lane = threadIdx.x & 31;
    int warp = threadIdx.x >> 5;
    __shared__ int wcnt[8];

    const int* erow = edge + (size_t)row * N;
    int cnt = 0;
#pragma unroll 4
    for (int w = 0; w < 32; ++w) {
        int col = warp * 1024 + w * 32 + lane;
        unsigned mask = __ballot_sync(0xFFFFFFFFu, erow[col] != 0);
        if (lane == 0) {
            g_bits[(size_t)row * WORDS + warp * 32 + w] = mask;
            cnt += __popc(mask);
        }
    }
    if (lane == 0) wcnt[warp] = cnt;
    __syncthreads();
    if (threadIdx.x == 0) {
        int deg = 1;
#pragma unroll
        for (int i = 0; i < 8; ++i) deg += wcnt[i];
        g_dinv[row] = rsqrtf((float)deg);
    }
}

// spacer (keeps big_gcn at profile position 4)
__global__ void noop_kernel() {}

// ---------------------------------------------------------------------------
// 2) small GEMM: yd = dinv_r * (act @ W) -> ydf + hi/lo.  Optional dual weights.
// ---------------------------------------------------------------------------
template <int KIN, int COUT>
__global__ void __launch_bounds__(256) small_gemm5(const float* __restrict__ act_ext,
                                                   int act_sel, int act_ld, int act_c0,
                                                   const float* __restrict__ Wa,
                                                   const float* __restrict__ Wb,
                                                   int out_ld, int out_c0) {
    const float* act = (act_sel == 1) ? g_h : ((act_sel == 2) ? g_rexd : act_ext);
    __shared__ float sW[KIN * COUT];
    __shared__ float sact[16 * KIN];

    int tid = threadIdx.x;
    if (Wb == nullptr) {
        for (int i = tid; i < KIN * COUT; i += 256) sW[i] = Wa[i];
    } else {
        for (int i = tid; i < KIN * COUT; i += 256) {
            int k = i / COUT, c = i % COUT;
            sW[i] = (c < 64) ? Wa[k * 64 + c] : Wb[k * 64 + (c - 64)];
        }
    }

    int rbase = blockIdx.x * 16;
    for (int j = tid; j < 16 * KIN; j += 256) {
        int r = j / KIN, k = j - r * KIN;
        sact[j] = act[(size_t)(rbase + r) * act_ld + act_c0 + k];
    }
    __syncthreads();

    constexpr int TPR = COUT / 4;
    constexpr int RPI = 256 / TPR;

    int c4 = (tid % TPR) * 4;
    int ry0 = tid / TPR;

#pragma unroll
    for (int it = 0; it < 16; it += RPI) {
        int ry = it + ry0;
        const float* sa = &sact[ry * KIN];
        float4 a0 = make_float4(0.f, 0.f, 0.f, 0.f);
        float4 a1 = make_float4(0.f, 0.f, 0.f, 0.f);
#pragma unroll
        for (int k = 0; k < KIN; k += 2) {
            float v0 = sa[k], v1 = sa[k + 1];
            float4 w0 = *(const float4*)&sW[k * COUT + c4];
            float4 w1 = *(const float4*)&sW[(k + 1) * COUT + c4];
            a0.x = fmaf(v0, w0.x, a0.x); a0.y = fmaf(v0, w0.y, a0.y);
            a0.z = fmaf(v0, w0.z, a0.z); a0.w = fmaf(v0, w0.w, a0.w);
            a1.x = fmaf(v1, w1.x, a1.x); a1.y = fmaf(v1, w1.y, a1.y);
            a1.z = fmaf(v1, w1.z, a1.z); a1.w = fmaf(v1, w1.w, a1.w);
        }
        int row = rbase + ry;
        float di = g_dinv[row];
        float4 y;
        y.x = di * (a0.x + a1.x); y.y = di * (a0.y + a1.y);
        y.z = di * (a0.z + a1.z); y.w = di * (a0.w + a1.w);

        size_t o = (size_t)row * out_ld + out_c0 + c4;
        *(float4*)&g_ydf[o] = y;

        float hx = __bfloat162float(__float2bfloat16(y.x));
        float hy = __bfloat162float(__float2bfloat16(y.y));
        float hz = __bfloat162float(__float2bfloat16(y.z));
        float hw = __bfloat162float(__float2bfloat16(y.w));
        *(uint2*)&g_ydh[o] = make_uint2(pack2bf(hx, hy), pack2bf(hz, hw));
        *(uint2*)&g_ydl[o] = make_uint2(pack2bf(y.x - hx, y.y - hy), pack2bf(y.z - hz, y.w - hw));
    }
}

// ---------------------------------------------------------------------------
// 3) big adjacency GEMM v6 (split-K, pipelined bitmask load)
//    grid (rows, cols, KSPLIT).  Raw fp32 partials out.
// ---------------------------------------------------------------------------
constexpr int SMEM_BG = (2 * 128 * 72 + 4 * 64 * 72) * 2;  // 73728 B

template <int KSPLIT>
__global__ void __launch_bounds__(256, 2) big_gcn6(int PW) {
    constexpr int BM  = 128;
    constexpr int KC  = 64;
    constexpr int NC  = (N / KSPLIT) / KC;
    constexpr int LDA = 72;
    constexpr int LDB = 72;
    constexpr int ASZ = BM * LDA;
    constexpr int BSZ = KC * LDB;
    constexpr int WM  = 32;
    constexpr int FM  = 2;

    extern __shared__ __align__(16) __nv_bfloat16 smem[];
    __nv_bfloat16* sA  = smem;
    __nv_bfloat16* sBh = smem + 2 * ASZ;
    __nv_bfloat16* sBl = smem + 2 * ASZ + 2 * BSZ;

    int tid  = threadIdx.x;
    int warp = tid >> 5;
    int wr   = warp >> 1;
    int wc   = warp & 1;
    int r0   = blockIdx.x * BM;
    int c0   = blockIdx.y * 64;
    int ks0  = blockIdx.z * (N / KSPLIT);

    // A expansion mapping: 2 threads per row, 32 bits each
    int arow = tid >> 1;
    const uint32_t* wptr = &g_bits[(size_t)(r0 + arow) * WORDS + (ks0 >> 5) + (tid & 1)];
    uint32_t abase = (uint32_t)__cvta_generic_to_shared(
        &sA[arow * LDA + (tid & 1) * 32]);

    wmma::fragment<wmma::accumulator, 16, 16, 16, float> acc[FM][2];
#pragma unroll
    for (int fm = 0; fm < FM; ++fm)
#pragma unroll
        for (int fn = 0; fn < 2; ++fn) wmma::fill_fragment(acc[fm][fn], 0.f);

    auto fetchB = [&](int ch, int buf) {
        int k0 = ks0 + ch * KC;
#pragma unroll
        for (int s = tid; s < 512; s += 256) {
            int row = s >> 3, seg = s & 7;
            size_t g = (size_t)(k0 + row) * PW + c0 + seg * 8;
            cp16(&sBh[buf * BSZ + row * LDB + seg * 8], &g_ydh[g]);
            cp16(&sBl[buf * BSZ + row * LDB + seg * 8], &g_ydl[g]);
        }
        cp_commit();
    };
    auto storeA = [&](uint32_t w, int buf) {
        uint32_t base = abase + buf * (ASZ * 2);  // bytes
#pragma unroll
        for (int j = 0; j < 4; ++j) {
            uint32_t bb = w >> (j * 8);
            uint4 u;
            u.x = ((bb & 1u)  ? 0x3F80u : 0u) | ((bb & 2u)   ? 0x3F800000u : 0u);
            u.y = ((bb & 4u)  ? 0x3F80u : 0u) | ((bb & 8u)   ? 0x3F800000u : 0u);
            u.z = ((bb & 16u) ? 0x3F80u : 0u) | ((bb & 32u)  ? 0x3F800000u : 0u);
            u.w = ((bb & 64u) ? 0x3F80u : 0u) | ((bb & 128u) ? 0x3F800000u : 0u);
            asm volatile("st.shared.v4.b32 [%0], {%1, %2, %3, %4};"
                         :: "r"(base + j * 16), "r"(u.x), "r"(u.y), "r"(u.z), "r"(u.w));
        }
    };

    // prologue
    fetchB(0, 0);
    storeA(wptr[0], 0);
    cp_wait0();
    __syncthreads();

    int buf = 0;
    for (int ch = 0; ch < NC; ++ch) {
        int nbuf = buf ^ 1;
        uint32_t wnext = 0;
        if (ch + 1 < NC) {
            fetchB(ch + 1, nbuf);
            wnext = wptr[(ch + 1) * 2];   // LDG issued before compute (latency hidden)
        }
#pragma unroll
        for (int ks = 0; ks < 4; ++ks) {
            wmma::fragment<wmma::matrix_a, 16, 16, 16, __nv_bfloat16, wmma::row_major> a[FM];
#pragma unroll
            for (int fm = 0; fm < FM; ++fm)
                wmma::load_matrix_sync(a[fm],
                    &sA[buf * ASZ + (wr * WM + fm * 16) * LDA + ks * 16], LDA);
#pragma unroll
            for (int fn = 0; fn < 2; ++fn) {
                wmma::fragment<wmma::matrix_b, 16, 16, 16, __nv_bfloat16, wmma::row_major> bh, bl;
                int bcol = wc * 32 + fn * 16;
                wmma::load_matrix_sync(bh, &sBh[buf * BSZ + (ks * 16) * LDB + bcol], LDB);
                wmma::load_matrix_sync(bl, &sBl[buf * BSZ + (ks * 16) * LDB + bcol], LDB);
#pragma unroll
                for (int fm = 0; fm < FM; ++fm) {
                    wmma::mma_sync(acc[fm][fn], a[fm], bh, acc[fm][fn]);
                    wmma::mma_sync(acc[fm][fn], a[fm], bl, acc[fm][fn]);
                }
            }
        }
        if (ch + 1 < NC) {
            storeA(wnext, nbuf);
            cp_wait0();
        }
        __syncthreads();
        buf = nbuf;
    }

    float* pout = &g_part[(size_t)blockIdx.z * N * PW];
#pragma unroll
    for (int fm = 0; fm < FM; ++fm)
#pragma unroll
        for (int fn = 0; fn < 2; ++fn)
            wmma::store_matrix_sync(
                &pout[(size_t)(r0 + wr * WM + fm * 16) * PW + c0 + wc * 32 + fn * 16],
                acc[fm][fn], PW, wmma::mem_row_major);
}

// ---------------------------------------------------------------------------
// 3b) combine: out = lrelu(dinv_i*(sum_p part_p + yd_i) + bias)
// ---------------------------------------------------------------------------
__global__ void __launch_bounds__(256) combine_kernel(const float* __restrict__ bias_a,
                                                      const float* __restrict__ bias_b,
                                                      int bsplit, int C, int nparts,
                                                      float* out_ext, int dest_sel,
                                                      int out_ld) {
    float* out = (dest_sel == 0) ? g_h : ((dest_sel == 1) ? g_rexd : out_ext);
    int i = blockIdx.x * 256 + threadIdx.x;
    int cq = C >> 2;
    int row = i / cq;
    int c4  = (i - row * cq) * 4;
    float di = g_dinv[row];
    size_t o = (size_t)row * C + c4;
    float4 s = *(const float4*)&g_ydf[o];
    for (int p = 0; p < nparts; ++p) {
        float4 pp = *(const float4*)&g_part[(size_t)p * N * C + o];
        s.x += pp.x; s.y += pp.y; s.z += pp.z; s.w += pp.w;
    }
    const float* bias = (c4 < bsplit) ? bias_a : bias_b;
    int bo = (c4 < bsplit) ? c4 : c4 - bsplit;
    float4 v;
    v.x = di * s.x + bias[bo + 0];
    v.y = di * s.y + bias[bo + 1];
    v.z = di * s.z + bias[bo + 2];
    v.w = di * s.w + bias[bo + 3];
    v.x = (v.x > 0.f) ? v.x : 0.01f * v.x;
    v.y = (v.y > 0.f) ? v.y : 0.01f * v.y;
    v.z = (v.z > 0.f) ? v.z : 0.01f * v.z;
    v.w = (v.w > 0.f) ? v.w : 0.01f * v.w;
    *(float4*)&out[(size_t)row * out_ld + c4] = v;
}

// ---------------------------------------------------------------------------
// 4) split re into hi/lo
// ---------------------------------------------------------------------------
__global__ void split_re_kernel() {
    int i = blockIdx.x * blockDim.x + threadIdx.x;
    int r = i >> 6, c = i & 63;
    float v = g_rexd[r * 128 + c];
    __nv_bfloat16 hi = __float2bfloat16(v);
    g_reh[i] = hi;
    g_rel[i] = __float2bfloat16(v - __bfloat162float(hi));
}

// ---------------------------------------------------------------------------
// 5) recon = sigmoid(re @ re^T), symmetric
// ---------------------------------------------------------------------------
__device__ __forceinline__ float fsig(float x) {
    return __fdividef(1.f, 1.f + __expf(-x));
}

__global__ void __launch_bounds__(256) recon_kernel(float* __restrict__ out) {
    if (blockIdx.x < blockIdx.y) return;

    constexpr int LD  = 72;
    constexpr int LDC = 68;
    __shared__ alignas(32) __nv_bfloat16 smem[4 * 64 * LD];
    __nv_bfloat16* sAh = smem;
    __nv_bfloat16* sAl = smem + 1 * 64 * LD;
    __nv_bfloat16* sBh = smem + 2 * 64 * LD;
    __nv_bfloat16* sBl = smem + 3 * 64 * LD;

    int tid = threadIdx.x;
    int r0 = blockIdx.y * 64, c0 = blockIdx.x * 64;

    int lr = tid >> 2, lc = (tid & 3) << 4;
    {
        const uint4* sh = (const uint4*)&g_reh[(size_t)(r0 + lr) * 64 + lc];
        const uint4* sl = (const uint4*)&g_rel[(size_t)(r0 + lr) * 64 + lc];
        uint4* dh = (uint4*)&sAh[lr * LD + lc];
        uint4* dl = (uint4*)&sAl[lr * LD + lc];
        dh[0] = sh[0]; dh[1] = sh[1];
        dl[0] = sl[0]; dl[1] = sl[1];
        const uint4* th = (const uint4*)&g_reh[(size_t)(c0 + lr) * 64 + lc];
        const uint4* tl = (const uint4*)&g_rel[(size_t)(c0 + lr) * 64 + lc];
        uint4* eh = (uint4*)&sBh[lr * LD + lc];
        uint4* el = (uint4*)&sBl[lr * LD + lc];
        eh[0] = th[0]; eh[1] = th[1];
        el[0] = tl[0]; el[1] = tl[1];
    }
    __syncthreads();

    int warp = tid >> 5;
    int lane = tid & 31;
    int wr = warp >> 1, wc = warp & 1;

    wmma::fragment<wmma::accumulator, 16, 16, 16, float> acc[2];
    wmma::fill_fragment(acc[0], 0.f);
    wmma::fill_fragment(acc[1], 0.f);

#pragma unroll
    for (int kc = 0; kc < 4; ++kc) {
        int k = kc * 16;
        wmma::fragment<wmma::matrix_a, 16, 16, 16, __nv_bfloat16, wmma::row_major> ah, al;
        wmma::load_matrix_sync(ah, &sAh[(wr * 16) * LD + k], LD);
        wmma::load_matrix_sync(al, &sAl[(wr * 16) * LD + k], LD);
#pragma unroll
        for (int j = 0; j < 2; ++j) {
            int col = wc * 32 + j * 16;
            wmma::fragment<wmma::matrix_b, 16, 16, 16, __nv_bfloat16, wmma::col_major> bh, bl;
            wmma::load_matrix_sync(bh, &sBh[col * LD + k], LD);
            wmma::load_matrix_sync(bl, &sBl[col * LD + k], LD);
            wmma::mma_sync(acc[j], ah, bh, acc[j]);
            wmma::mma_sync(acc[j], ah, bl, acc[j]);
            wmma::mma_sync(acc[j], al, bh, acc[j]);
        }
    }
    __syncthreads();

    float* sC = reinterpret_cast<float*>(smem);
#pragma unroll
    for (int j = 0; j < 2; ++j)
        wmma::store_matrix_sync(&sC[(wr * 16) * LDC + wc * 32 + j * 16], acc[j], LDC,
                                wmma::mem_row_major);
    __syncthreads();

    // direct tile (vectorized, coalesced)
#pragma unroll
    for (int it = 0; it < 4; ++it) {
        int f4 = tid + it * 256;
        int r  = f4 >> 4;
        int c4 = (f4 & 15) << 2;
        float4 o;
        o.x = fsig(sC[r * LDC + c4 + 0]);
        o.y = fsig(sC[r * LDC + c4 + 1]);
        o.z = fsig(sC[r * LDC + c4 + 2]);
        o.w = fsig(sC[r * LDC + c4 + 3]);
        *(float4*)&out[(size_t)(r0 + r) * N + c0 + c4] = o;
    }
    // transposed tile: lane-major (conflict-free LDS, coalesced STG.32)
    if (blockIdx.x != blockIdx.y) {
#pragma unroll
        for (int i = 0; i < 8; ++i) {
            int c = warp * 8 + i;          // sC column -> transposed row
            float v0 = sC[c * LDC + lane];
            float v1 = sC[c * LDC + 32 + lane];
            out[(size_t)(c0 + c) * N + r0 + lane]      = fsig(v0);
            out[(size_t)(c0 + c) * N + r0 + 32 + lane] = fsig(v1);
        }
    }
}

// ---------------------------------------------------------------------------
// Launch chain (position 4 = big_gcn6 -> gets profiled)
// ---------------------------------------------------------------------------
extern "C" void kernel_launch(void* const* d_in, const int* in_sizes, int n_in,
                              void* d_out, int out_size) {
    (void)in_sizes; (void)n_in; (void)out_size;
    const float* x    = (const float*)d_in[0];
    const int*   edge = (const int*)  d_in[1];
    const float* W1   = (const float*)d_in[2];
    const float* b1   = (const float*)d_in[3];
    const float* W2   = (const float*)d_in[4];
    const float* b2   = (const float*)d_in[5];
    const float* We   = (const float*)d_in[6];
    const float* be   = (const float*)d_in[7];
    const float* Wd1  = (const float*)d_in[8];
    const float* bd1  = (const float*)d_in[9];
    const float* Wd2  = (const float*)d_in[10];
    const float* bd2  = (const float*)d_in[11];

    float* out   = (float*)d_out;
    float* recon = out;
    float* xout  = out + (size_t)N * N;
    float* zout  = xout + (size_t)N * 128;

    cudaFuncSetAttribute(big_gcn6<4>, cudaFuncAttributeMaxDynamicSharedMemorySize, SMEM_BG);
    cudaFuncSetAttribute(big_gcn6<2>, cudaFuncAttributeMaxDynamicSharedMemorySize, SMEM_BG);

    prep_kernel<<<N, 256>>>(edge);                                            // 1
    small_gemm5<128, 64><<<512, 256>>>(x, 0, 128, 0, W1, nullptr, 64, 0);     // 2
    noop_kernel<<<1, 32>>>();                                                 // 3 (spacer)

    // layer 1: h = lrelu(nadj @ (x@W1) + b1)   [N,64]   split-K=4
    big_gcn6<4><<<dim3(64, 1, 4), 256, SMEM_BG>>>(64);                        // 4 <- profiled
    combine_kernel<<<N * 64 / 1024, 256>>>(b1, b1, 64, 64, 4, nullptr, 0, 64); // 5

    // layer 2: z = lrelu(nadj @ (h@W2) + b2)   [N,128]
    small_gemm5<64, 128><<<512, 256>>>(nullptr, 1, 64, 0, W2, nullptr, 128, 0);    // 6
    big_gcn6<2><<<dim3(64, 2, 2), 256, SMEM_BG>>>(128);                            // 7
    combine_kernel<<<N * 128 / 1024, 256>>>(b2, b2, 128, 128, 2, zout, 2, 128);    // 8

    // layers 3+4 fused: [re | xd] = lrelu(nadj @ (z@[We|Wd1]) + [be|bd1])
    small_gemm5<128, 128><<<512, 256>>>(zout, 0, 128, 0, We, Wd1, 128, 0);         // 9
    big_gcn6<2><<<dim3(64, 2, 2), 256, SMEM_BG>>>(128);                            // 10
    combine_kernel<<<N * 128 / 1024, 256>>>(be, bd1, 64, 128, 2, nullptr, 1, 128); // 11

    split_re_kernel<<<(N * 64) / 256, 256>>>();                                    // 12

    // layer 5: x_out = lrelu(nadj @ (xd@Wd2) + bd2)  [N,128]
    small_gemm5<64, 128><<<512, 256>>>(nullptr, 2, 128, 64, Wd2, nullptr, 128, 0); // 13
    big_gcn6<2><<<dim3(64, 2, 2), 256, SMEM_BG>>>(128);                            // 14
    combine_kernel<<<N * 128 / 1024, 256>>>(bd2, bd2, 128, 128, 2, xout, 2, 128);  // 15

    // recon = sigmoid(re @ re^T)
    recon_kernel<<<dim3(128, 128), 256>>>(recon);                                  // 16
}

// round 7
// speedup vs baseline: 1.6359x; 1.1718x over previous
#include <cuda_runtime.h>
#include <cuda_bf16.h>
#include <mma.h>
#include <stdint.h>

using namespace nvcuda;

constexpr int N     = 8192;
constexpr int WORDS = N / 32;

// ---------------------------------------------------------------------------
// Scratch
// ---------------------------------------------------------------------------
__device__ uint32_t       g_bits[(size_t)N * WORDS];   // 8 MB adjacency bitmask
__device__ float          g_dinv[N];
__device__ float          g_ydf[(size_t)N * 128];      // dinv_j * (Y@W) fp32 [row][col]
__device__ __nv_bfloat16  g_ydh[(size_t)N * 128];      // hi split
__device__ __nv_bfloat16  g_ydl[(size_t)N * 128];      // lo split
__device__ float          g_part[4 * (size_t)N * 128]; // split-K partials (fp32)
__device__ float          g_h[(size_t)N * 64];
__device__ float          g_rexd[(size_t)N * 128];     // [re | xd]
__device__ __nv_bfloat16  g_reh[(size_t)N * 64];
__device__ __nv_bfloat16  g_rel[(size_t)N * 64];

// ---------------------------------------------------------------------------
// cp.async helpers
// ---------------------------------------------------------------------------
__device__ __forceinline__ void cp16(void* smem_dst, const void* gsrc) {
    uint32_t d = (uint32_t)__cvta_generic_to_shared(smem_dst);
    asm volatile("cp.async.cg.shared.global [%0], [%1], 16;\n" :: "r"(d), "l"(gsrc));
}
__device__ __forceinline__ void cp_commit() {
    asm volatile("cp.async.commit_group;\n" ::: "memory");
}
__device__ __forceinline__ void cp_wait0() {
    asm volatile("cp.async.wait_group 0;\n" ::: "memory");
}
__device__ __forceinline__ uint32_t pack2bf(float a, float b) {
    __nv_bfloat162 t = __floats2bfloat162_rn(a, b);
    return *(uint32_t*)&t;
}

// ---------------------------------------------------------------------------
// 1) Prep: bitmask + dinv
// ---------------------------------------------------------------------------
__global__ void __launch_bounds__(256) prep_kernel(const int* __restrict__ edge) {
    int row  = blockIdx.x;
    int lane = threadIdx.x & 31;
    int warp = threadIdx.x >> 5;
    __shared__ int wcnt[8];

    const int* erow = edge + (size_t)row * N;
    int cnt = 0;
#pragma unroll 4
    for (int w = 0; w < 32; ++w) {
        int col = warp * 1024 + w * 32 + lane;
        unsigned mask = __ballot_sync(0xFFFFFFFFu, erow[col] != 0);
        if (lane == 0) {
            g_bits[(size_t)row * WORDS + warp * 32 + w] = mask;
            cnt += __popc(mask);
        }
    }
    if (lane == 0) wcnt[warp] = cnt;
    __syncthreads();
    if (threadIdx.x == 0) {
        int deg = 1;
#pragma unroll
        for (int i = 0; i < 8; ++i) deg += wcnt[i];
        g_dinv[row] = rsqrtf((float)deg);
    }
}

// spacer (keeps big_gcn at profile position 4)
__global__ void noop_kernel() {}

// ---------------------------------------------------------------------------
// 2) small GEMM: yd = dinv_r * (act @ W) -> ydf + hi/lo.  Optional dual weights.
// ---------------------------------------------------------------------------
template <int KIN, int COUT>
__global__ void __launch_bounds__(256) small_gemm5(const float* __restrict__ act_ext,
                                                   int act_sel, int act_ld, int act_c0,
                                                   const float* __restrict__ Wa,
                                                   const float* __restrict__ Wb,
                                                   int out_ld, int out_c0) {
    const float* act = (act_sel == 1) ? g_h : ((act_sel == 2) ? g_rexd : act_ext);
    __shared__ float sW[KIN * COUT];
    __shared__ float sact[16 * KIN];

    int tid = threadIdx.x;
    if (Wb == nullptr) {
        for (int i = tid; i < KIN * COUT; i += 256) sW[i] = Wa[i];
    } else {
        for (int i = tid; i < KIN * COUT; i += 256) {
            int k = i / COUT, c = i % COUT;
            sW[i] = (c < 64) ? Wa[k * 64 + c] : Wb[k * 64 + (c - 64)];
        }
    }

    int rbase = blockIdx.x * 16;
    for (int j = tid; j < 16 * KIN; j += 256) {
        int r = j / KIN, k = j - r * KIN;
        sact[j] = act[(size_t)(rbase + r) * act_ld + act_c0 + k];
    }
    __syncthreads();

    constexpr int TPR = COUT / 4;
    constexpr int RPI = 256 / TPR;

    int c4 = (tid % TPR) * 4;
    int ry0 = tid / TPR;

#pragma unroll
    for (int it = 0; it < 16; it += RPI) {
        int ry = it + ry0;
        const float* sa = &sact[ry * KIN];
        float4 a0 = make_float4(0.f, 0.f, 0.f, 0.f);
        float4 a1 = make_float4(0.f, 0.f, 0.f, 0.f);
#pragma unroll
        for (int k = 0; k < KIN; k += 2) {
            float v0 = sa[k], v1 = sa[k + 1];
            float4 w0 = *(const float4*)&sW[k * COUT + c4];
            float4 w1 = *(const float4*)&sW[(k + 1) * COUT + c4];
            a0.x = fmaf(v0, w0.x, a0.x); a0.y = fmaf(v0, w0.y, a0.y);
            a0.z = fmaf(v0, w0.z, a0.z); a0.w = fmaf(v0, w0.w, a0.w);
            a1.x = fmaf(v1, w1.x, a1.x); a1.y = fmaf(v1, w1.y, a1.y);
            a1.z = fmaf(v1, w1.z, a1.z); a1.w = fmaf(v1, w1.w, a1.w);
        }
        int row = rbase + ry;
        float di = g_dinv[row];
        float4 y;
        y.x = di * (a0.x + a1.x); y.y = di * (a0.y + a1.y);
        y.z = di * (a0.z + a1.z); y.w = di * (a0.w + a1.w);

        size_t o = (size_t)row * out_ld + out_c0 + c4;
        *(float4*)&g_ydf[o] = y;

        float hx = __bfloat162float(__float2bfloat16(y.x));
        float hy = __bfloat162float(__float2bfloat16(y.y));
        float hz = __bfloat162float(__float2bfloat16(y.z));
        float hw = __bfloat162float(__float2bfloat16(y.w));
        *(uint2*)&g_ydh[o] = make_uint2(pack2bf(hx, hy), pack2bf(hz, hw));
        *(uint2*)&g_ydl[o] = make_uint2(pack2bf(y.x - hx, y.y - hy), pack2bf(y.z - hz, y.w - hw));
    }
}

// ---------------------------------------------------------------------------
// 3) big adjacency GEMM v7: full-width CTA tile (BM=128 x BN), warp grid 2x4,
//    split-K=4, double-buffered cp.async B + pipelined bitmask A.
//    Partials to g_part[bz].
// ---------------------------------------------------------------------------
template <int BN>
__global__ void __launch_bounds__(256, 2) big_gcn7() {
    constexpr int KSPLIT = 4;
    constexpr int BM  = 128;
    constexpr int KC  = 64;
    constexpr int NC  = (N / KSPLIT) / KC;   // 32 chunks
    constexpr int LDA = 72;
    constexpr int LDB = BN + 8;
    constexpr int ASZ = BM * LDA;
    constexpr int BSZ = KC * LDB;
    constexpr int WN  = BN / 4;              // warp cols (2 rows x 4 cols grid)
    constexpr int FM  = 4;                   // 64 rows / 16
    constexpr int FN  = WN / 16;             // 2 (BN=128) or 1 (BN=64)
    constexpr int SEG = BN / 8;              // cp16 segments per B row
    constexpr int CPB = KC * SEG / 256;      // cp16 per thread per (h|l)

    extern __shared__ __align__(16) __nv_bfloat16 smem[];
    __nv_bfloat16* sA  = smem;                       // [2][ASZ]
    __nv_bfloat16* sBh = smem + 2 * ASZ;             // [2][BSZ]
    __nv_bfloat16* sBl = smem + 2 * ASZ + 2 * BSZ;   // [2][BSZ]

    int tid  = threadIdx.x;
    int warp = tid >> 5;
    int wr   = warp >> 2;     // 0..1
    int wc   = warp & 3;      // 0..3
    int r0   = blockIdx.x * BM;
    int ks0  = blockIdx.z * (N / KSPLIT);

    // A expansion mapping: 2 threads per row, 32 bits each
    int arow = tid >> 1;
    const uint32_t* wptr = &g_bits[(size_t)(r0 + arow) * WORDS + (ks0 >> 5) + (tid & 1)];
    uint32_t abase = (uint32_t)__cvta_generic_to_shared(&sA[arow * LDA + (tid & 1) * 32]);

    wmma::fragment<wmma::accumulator, 16, 16, 16, float> acc[FM][FN];
#pragma unroll
    for (int fm = 0; fm < FM; ++fm)
#pragma unroll
        for (int fn = 0; fn < FN; ++fn) wmma::fill_fragment(acc[fm][fn], 0.f);

    auto fetchB = [&](int ch, int buf) {
        int k0 = ks0 + ch * KC;
#pragma unroll
        for (int i = 0; i < CPB; ++i) {
            int s = tid + i * 256;
            int row = s / SEG, seg = s % SEG;
            size_t g = (size_t)(k0 + row) * BN + seg * 8;
            cp16(&sBh[buf * BSZ + row * LDB + seg * 8], &g_ydh[g]);
            cp16(&sBl[buf * BSZ + row * LDB + seg * 8], &g_ydl[g]);
        }
        cp_commit();
    };
    auto storeA = [&](uint32_t w, int buf) {
        uint32_t base = abase + buf * (ASZ * 2);  // bytes
#pragma unroll
        for (int j = 0; j < 4; ++j) {
            uint32_t bb = w >> (j * 8);
            uint4 u;
            u.x = ((bb & 1u)  ? 0x3F80u : 0u) | ((bb & 2u)   ? 0x3F800000u : 0u);
            u.y = ((bb & 4u)  ? 0x3F80u : 0u) | ((bb & 8u)   ? 0x3F800000u : 0u);
            u.z = ((bb & 16u) ? 0x3F80u : 0u) | ((bb & 32u)  ? 0x3F800000u : 0u);
            u.w = ((bb & 64u) ? 0x3F80u : 0u) | ((bb & 128u) ? 0x3F800000u : 0u);
            asm volatile("st.shared.v4.b32 [%0], {%1, %2, %3, %4};"
                         :: "r"(base + j * 16), "r"(u.x), "r"(u.y), "r"(u.z), "r"(u.w));
        }
    };

    // prologue
    fetchB(0, 0);
    storeA(wptr[0], 0);
    cp_wait0();
    __syncthreads();

    int buf = 0;
    for (int ch = 0; ch < NC; ++ch) {
        int nbuf = buf ^ 1;
        uint32_t wnext = 0;
        if (ch + 1 < NC) {
            fetchB(ch + 1, nbuf);
            wnext = wptr[(ch + 1) * 2];   // LDG hidden under compute
        }
#pragma unroll
        for (int ks = 0; ks < 4; ++ks) {
            wmma::fragment<wmma::matrix_a, 16, 16, 16, __nv_bfloat16, wmma::row_major> a[FM];
#pragma unroll
            for (int fm = 0; fm < FM; ++fm)
                wmma::load_matrix_sync(a[fm],
                    &sA[buf * ASZ + (wr * 64 + fm * 16) * LDA + ks * 16], LDA);
#pragma unroll
            for (int fn = 0; fn < FN; ++fn) {
                wmma::fragment<wmma::matrix_b, 16, 16, 16, __nv_bfloat16, wmma::row_major> bh, bl;
                int bcol = wc * WN + fn * 16;
                wmma::load_matrix_sync(bh, &sBh[buf * BSZ + (ks * 16) * LDB + bcol], LDB);
                wmma::load_matrix_sync(bl, &sBl[buf * BSZ + (ks * 16) * LDB + bcol], LDB);
#pragma unroll
                for (int fm = 0; fm < FM; ++fm) {
                    wmma::mma_sync(acc[fm][fn], a[fm], bh, acc[fm][fn]);
                    wmma::mma_sync(acc[fm][fn], a[fm], bl, acc[fm][fn]);
                }
            }
        }
        if (ch + 1 < NC) {
            storeA(wnext, nbuf);
            cp_wait0();
        }
        __syncthreads();
        buf = nbuf;
    }

    float* pout = &g_part[(size_t)blockIdx.z * N * BN];
#pragma unroll
    for (int fm = 0; fm < FM; ++fm)
#pragma unroll
        for (int fn = 0; fn < FN; ++fn)
            wmma::store_matrix_sync(
                &pout[(size_t)(r0 + wr * 64 + fm * 16) * BN + wc * WN + fn * 16],
                acc[fm][fn], BN, wmma::mem_row_major);
}

constexpr int SMEM_BG7_128 = (2 * 128 * 72 + 4 * 64 * 136) * 2;  // 106496 B
constexpr int SMEM_BG7_64  = (2 * 128 * 72 + 4 * 64 * 72) * 2;   //  73728 B

// ---------------------------------------------------------------------------
// 3b) combine: out = lrelu(dinv_i*(sum_p part_p + yd_i) + bias)
// ---------------------------------------------------------------------------
__global__ void __launch_bounds__(256) combine_kernel(const float* __restrict__ bias_a,
                                                      const float* __restrict__ bias_b,
                                                      int bsplit, int C,
                                                      float* out_ext, int dest_sel,
                                                      int out_ld) {
    float* out = (dest_sel == 0) ? g_h : ((dest_sel == 1) ? g_rexd : out_ext);
    int i = blockIdx.x * 256 + threadIdx.x;
    int cq = C >> 2;
    int row = i / cq;
    int c4  = (i - row * cq) * 4;
    float di = g_dinv[row];
    size_t o = (size_t)row * C + c4;
    float4 s = *(const float4*)&g_ydf[o];
#pragma unroll
    for (int p = 0; p < 4; ++p) {
        float4 pp = *(const float4*)&g_part[(size_t)p * N * C + o];
        s.x += pp.x; s.y += pp.y; s.z += pp.z; s.w += pp.w;
    }
    const float* bias = (c4 < bsplit) ? bias_a : bias_b;
    int bo = (c4 < bsplit) ? c4 : c4 - bsplit;
    float4 v;
    v.x = di * s.x + bias[bo + 0];
    v.y = di * s.y + bias[bo + 1];
    v.z = di * s.z + bias[bo + 2];
    v.w = di * s.w + bias[bo + 3];
    v.x = (v.x > 0.f) ? v.x : 0.01f * v.x;
    v.y = (v.y > 0.f) ? v.y : 0.01f * v.y;
    v.z = (v.z > 0.f) ? v.z : 0.01f * v.z;
    v.w = (v.w > 0.f) ? v.w : 0.01f * v.w;
    *(float4*)&out[(size_t)row * out_ld + c4] = v;
}

// ---------------------------------------------------------------------------
// 4) split re into hi/lo
// ---------------------------------------------------------------------------
__global__ void split_re_kernel() {
    int i = blockIdx.x * blockDim.x + threadIdx.x;
    int r = i >> 6, c = i & 63;
    float v = g_rexd[r * 128 + c];
    __nv_bfloat16 hi = __float2bfloat16(v);
    g_reh[i] = hi;
    g_rel[i] = __float2bfloat16(v - __bfloat162float(hi));
}

// ---------------------------------------------------------------------------
// 5) recon = sigmoid(re @ re^T), symmetric
// ---------------------------------------------------------------------------
__device__ __forceinline__ float fsig(float x) {
    return __fdividef(1.f, 1.f + __expf(-x));
}

__global__ void __launch_bounds__(256) recon_kernel(float* __restrict__ out) {
    if (blockIdx.x < blockIdx.y) return;

    constexpr int LD  = 72;
    constexpr int LDC = 68;
    __shared__ alignas(32) __nv_bfloat16 smem[4 * 64 * LD];
    __nv_bfloat16* sAh = smem;
    __nv_bfloat16* sAl = smem + 1 * 64 * LD;
    __nv_bfloat16* sBh = smem + 2 * 64 * LD;
    __nv_bfloat16* sBl = smem + 3 * 64 * LD;

    int tid = threadIdx.x;
    int r0 = blockIdx.y * 64, c0 = blockIdx.x * 64;

    int lr = tid >> 2, lc = (tid & 3) << 4;
    {
        const uint4* sh = (const uint4*)&g_reh[(size_t)(r0 + lr) * 64 + lc];
        const uint4* sl = (const uint4*)&g_rel[(size_t)(r0 + lr) * 64 + lc];
        uint4* dh = (uint4*)&sAh[lr * LD + lc];
        uint4* dl = (uint4*)&sAl[lr * LD + lc];
        dh[0] = sh[0]; dh[1] = sh[1];
        dl[0] = sl[0]; dl[1] = sl[1];
        const uint4* th = (const uint4*)&g_reh[(size_t)(c0 + lr) * 64 + lc];
        const uint4* tl = (const uint4*)&g_rel[(size_t)(c0 + lr) * 64 + lc];
        uint4* eh = (uint4*)&sBh[lr * LD + lc];
        uint4* el = (uint4*)&sBl[lr * LD + lc];
        eh[0] = th[0]; eh[1] = th[1];
        el[0] = tl[0]; el[1] = tl[1];
    }
    __syncthreads();

    int warp = tid >> 5;
    int lane = tid & 31;
    int wr = warp >> 1, wc = warp & 1;

    wmma::fragment<wmma::accumulator, 16, 16, 16, float> acc[2];
    wmma::fill_fragment(acc[0], 0.f);
    wmma::fill_fragment(acc[1], 0.f);

#pragma unroll
    for (int kc = 0; kc < 4; ++kc) {
        int k = kc * 16;
        wmma::fragment<wmma::matrix_a, 16, 16, 16, __nv_bfloat16, wmma::row_major> ah, al;
        wmma::load_matrix_sync(ah, &sAh[(wr * 16) * LD + k], LD);
        wmma::load_matrix_sync(al, &sAl[(wr * 16) * LD + k], LD);
#pragma unroll
        for (int j = 0; j < 2; ++j) {
            int col = wc * 32 + j * 16;
            wmma::fragment<wmma::matrix_b, 16, 16, 16, __nv_bfloat16, wmma::col_major> bh, bl;
            wmma::load_matrix_sync(bh, &sBh[col * LD + k], LD);
            wmma::load_matrix_sync(bl, &sBl[col * LD + k], LD);
            wmma::mma_sync(acc[j], ah, bh, acc[j]);
            wmma::mma_sync(acc[j], ah, bl, acc[j]);
            wmma::mma_sync(acc[j], al, bh, acc[j]);
        }
    }
    __syncthreads();

    float* sC = reinterpret_cast<float*>(smem);
#pragma unroll
    for (int j = 0; j < 2; ++j)
        wmma::store_matrix_sync(&sC[(wr * 16) * LDC + wc * 32 + j * 16], acc[j], LDC,
                                wmma::mem_row_major);
    __syncthreads();

#pragma unroll
    for (int it = 0; it < 4; ++it) {
        int f4 = tid + it * 256;
        int r  = f4 >> 4;
        int c4 = (f4 & 15) << 2;
        float4 o;
        o.x = fsig(sC[r * LDC + c4 + 0]);
        o.y = fsig(sC[r * LDC + c4 + 1]);
        o.z = fsig(sC[r * LDC + c4 + 2]);
        o.w = fsig(sC[r * LDC + c4 + 3]);
        *(float4*)&out[(size_t)(r0 + r) * N + c0 + c4] = o;
    }
    if (blockIdx.x != blockIdx.y) {
#pragma unroll
        for (int i = 0; i < 8; ++i) {
            int c = warp * 8 + i;
            float v0 = sC[c * LDC + lane];
            float v1 = sC[c * LDC + 32 + lane];
            out[(size_t)(c0 + c) * N + r0 + lane]      = fsig(v0);
            out[(size_t)(c0 + c) * N + r0 + 32 + lane] = fsig(v1);
        }
    }
}

// ---------------------------------------------------------------------------
// Launch chain (4th launch = big_gcn7<64> -> profiled)
// ---------------------------------------------------------------------------
extern "C" void kernel_launch(void* const* d_in, const int* in_sizes, int n_in,
                              void* d_out, int out_size) {
    (void)in_sizes; (void)n_in; (void)out_size;
    const float* x    = (const float*)d_in[0];
    const int*   edge = (const int*)  d_in[1];
    const float* W1   = (const float*)d_in[2];
    const float* b1   = (const float*)d_in[3];
    const float* W2   = (const float*)d_in[4];
    const float* b2   = (const float*)d_in[5];
    const float* We   = (const float*)d_in[6];
    const float* be   = (const float*)d_in[7];
    const float* Wd1  = (const float*)d_in[8];
    const float* bd1  = (const float*)d_in[9];
    const float* Wd2  = (const float*)d_in[10];
    const float* bd2  = (const float*)d_in[11];

    float* out   = (float*)d_out;
    float* recon = out;
    float* xout  = out + (size_t)N * N;
    float* zout  = xout + (size_t)N * 128;

    cudaFuncSetAttribute(big_gcn7<128>, cudaFuncAttributeMaxDynamicSharedMemorySize, SMEM_BG7_128);
    cudaFuncSetAttribute(big_gcn7<64>,  cudaFuncAttributeMaxDynamicSharedMemorySize, SMEM_BG7_64);

    prep_kernel<<<N, 256>>>(edge);                                            // 1
    small_gemm5<128, 64><<<512, 256>>>(x, 0, 128, 0, W1, nullptr, 64, 0);     // 2
    noop_kernel<<<1, 32>>>();                                                 // 3

    // layer 1: h = lrelu(nadj @ (x@W1) + b1)   [N,64]
    big_gcn7<64><<<dim3(64, 1, 4), 256, SMEM_BG7_64>>>();                     // 4 <- profiled
    combine_kernel<<<N * 64 / 1024, 256>>>(b1, b1, 64, 64, nullptr, 0, 64);   // 5

    // layer 2: z = lrelu(nadj @ (h@W2) + b2)   [N,128]
    small_gemm5<64, 128><<<512, 256>>>(nullptr, 1, 64, 0, W2, nullptr, 128, 0);    // 6
    big_gcn7<128><<<dim3(64, 1, 4), 256, SMEM_BG7_128>>>();                        // 7
    combine_kernel<<<N * 128 / 1024, 256>>>(b2, b2, 128, 128, zout, 2, 128);       // 8

    // layers 3+4 fused: [re | xd] = lrelu(nadj @ (z@[We|Wd1]) + [be|bd1])
    small_gemm5<128, 128><<<512, 256>>>(zout, 0, 128, 0, We, Wd1, 128, 0);         // 9
    big_gcn7<128><<<dim3(64, 1, 4), 256, SMEM_BG7_128>>>();                        // 10
    combine_kernel<<<N * 128 / 1024, 256>>>(be, bd1, 64, 128, nullptr, 1, 128);    // 11

    split_re_kernel<<<(N * 64) / 256, 256>>>();                                    // 12

    // layer 5: x_out = lrelu(nadj @ (xd@Wd2) + bd2)  [N,128]
    small_gemm5<64, 128><<<512, 256>>>(nullptr, 2, 128, 64, Wd2, nullptr, 128, 0); // 13
    big_gcn7<128><<<dim3(64, 1, 4), 256, SMEM_BG7_128>>>();                        // 14
    combine_kernel<<<N * 128 / 1024, 256>>>(bd2, bd2, 128, 128, xout, 2, 128);     // 15

    // recon = sigmoid(re @ re^T)
    recon_kernel<<<dim3(128, 128), 256>>>(recon);                                  // 16
}

// round 8
// speedup vs baseline: 1.6369x; 1.0006x over previous
#include <cuda_runtime.h>
#include <cuda_bf16.h>
#include <mma.h>
#include <stdint.h>

using namespace nvcuda;

constexpr int N     = 8192;
constexpr int WORDS = N / 32;

// ---------------------------------------------------------------------------
// Scratch
// ---------------------------------------------------------------------------
__device__ uint32_t       g_bits[(size_t)N * WORDS];   // 8 MB adjacency bitmask
__device__ float          g_dinv[N];
__device__ float          g_ydf[(size_t)N * 128];      // dinv_j * (Y@W) fp32 [row][col]
__device__ __nv_bfloat16  g_ydh[(size_t)N * 128];      // hi split
__device__ __nv_bfloat16  g_ydl[(size_t)N * 128];      // lo split
__device__ float          g_part[4 * (size_t)N * 128]; // split-K partials (fp32)
__device__ float          g_h[(size_t)N * 64];
__device__ float          g_rexd[(size_t)N * 128];     // [re | xd]
__device__ __nv_bfloat16  g_reh[(size_t)N * 64];
__device__ __nv_bfloat16  g_rel[(size_t)N * 64];

// ---------------------------------------------------------------------------
// cp.async helpers
// ---------------------------------------------------------------------------
__device__ __forceinline__ void cp16(void* smem_dst, const void* gsrc) {
    uint32_t d = (uint32_t)__cvta_generic_to_shared(smem_dst);
    asm volatile("cp.async.cg.shared.global [%0], [%1], 16;\n" :: "r"(d), "l"(gsrc));
}
__device__ __forceinline__ void cp_commit() {
    asm volatile("cp.async.commit_group;\n" ::: "memory");
}
__device__ __forceinline__ void cp_wait0() {
    asm volatile("cp.async.wait_group 0;\n" ::: "memory");
}
__device__ __forceinline__ uint32_t pack2bf(float a, float b) {
    __nv_bfloat162 t = __floats2bfloat162_rn(a, b);
    return *(uint32_t*)&t;
}

// ---------------------------------------------------------------------------
// 1) Prep: bitmask + dinv
// ---------------------------------------------------------------------------
__global__ void __launch_bounds__(256) prep_kernel(const int* __restrict__ edge) {
    int row  = blockIdx.x;
    int lane = threadIdx.x & 31;
    int warp = threadIdx.x >> 5;
    __shared__ int wcnt[8];

    const int* erow = edge + (size_t)row * N;
    int cnt = 0;
#pragma unroll 4
    for (int w = 0; w < 32; ++w) {
        int col = warp * 1024 + w * 32 + lane;
        unsigned mask = __ballot_sync(0xFFFFFFFFu, erow[col] != 0);
        if (lane == 0) {
            g_bits[(size_t)row * WORDS + warp * 32 + w] = mask;
            cnt += __popc(mask);
        }
    }
    if (lane == 0) wcnt[warp] = cnt;
    __syncthreads();
    if (threadIdx.x == 0) {
        int deg = 1;
#pragma unroll
        for (int i = 0; i < 8; ++i) deg += wcnt[i];
        g_dinv[row] = rsqrtf((float)deg);
    }
}

// spacer (keeps big_gcn at profile position 4)
__global__ void noop_kernel() {}

// ---------------------------------------------------------------------------
// 2) small GEMM: yd = dinv_r * (act @ W) -> ydf + hi/lo.  Optional dual weights.
// ---------------------------------------------------------------------------
template <int KIN, int COUT>
__global__ void __launch_bounds__(256) small_gemm5(const float* __restrict__ act_ext,
                                                   int act_sel, int act_ld, int act_c0,
                                                   const float* __restrict__ Wa,
                                                   const float* __restrict__ Wb,
                                                   int out_ld, int out_c0) {
    const float* act = (act_sel == 1) ? g_h : ((act_sel == 2) ? g_rexd : act_ext);
    __shared__ float sW[KIN * COUT];
    __shared__ float sact[16 * KIN];

    int tid = threadIdx.x;
    if (Wb == nullptr) {
        for (int i = tid; i < KIN * COUT; i += 256) sW[i] = Wa[i];
    } else {
        for (int i = tid; i < KIN * COUT; i += 256) {
            int k = i / COUT, c = i % COUT;
            sW[i] = (c < 64) ? Wa[k * 64 + c] : Wb[k * 64 + (c - 64)];
        }
    }

    int rbase = blockIdx.x * 16;
    for (int j = tid; j < 16 * KIN; j += 256) {
        int r = j / KIN, k = j - r * KIN;
        sact[j] = act[(size_t)(rbase + r) * act_ld + act_c0 + k];
    }
    __syncthreads();

    constexpr int TPR = COUT / 4;
    constexpr int RPI = 256 / TPR;

    int c4 = (tid % TPR) * 4;
    int ry0 = tid / TPR;

#pragma unroll
    for (int it = 0; it < 16; it += RPI) {
        int ry = it + ry0;
        const float* sa = &sact[ry * KIN];
        float4 a0 = make_float4(0.f, 0.f, 0.f, 0.f);
        float4 a1 = make_float4(0.f, 0.f, 0.f, 0.f);
#pragma unroll
        for (int k = 0; k < KIN; k += 2) {
            float v0 = sa[k], v1 = sa[k + 1];
            float4 w0 = *(const float4*)&sW[k * COUT + c4];
            float4 w1 = *(const float4*)&sW[(k + 1) * COUT + c4];
            a0.x = fmaf(v0, w0.x, a0.x); a0.y = fmaf(v0, w0.y, a0.y);
            a0.z = fmaf(v0, w0.z, a0.z); a0.w = fmaf(v0, w0.w, a0.w);
            a1.x = fmaf(v1, w1.x, a1.x); a1.y = fmaf(v1, w1.y, a1.y);
            a1.z = fmaf(v1, w1.z, a1.z); a1.w = fmaf(v1, w1.w, a1.w);
        }
        int row = rbase + ry;
        float di = g_dinv[row];
        float4 y;
        y.x = di * (a0.x + a1.x); y.y = di * (a0.y + a1.y);
        y.z = di * (a0.z + a1.z); y.w = di * (a0.w + a1.w);

        size_t o = (size_t)row * out_ld + out_c0 + c4;
        *(float4*)&g_ydf[o] = y;

        float hx = __bfloat162float(__float2bfloat16(y.x));
        float hy = __bfloat162float(__float2bfloat16(y.y));
        float hz = __bfloat162float(__float2bfloat16(y.z));
        float hw = __bfloat162float(__float2bfloat16(y.w));
        *(uint2*)&g_ydh[o] = make_uint2(pack2bf(hx, hy), pack2bf(hz, hw));
        *(uint2*)&g_ydl[o] = make_uint2(pack2bf(y.x - hx, y.y - hy), pack2bf(y.z - hz, y.w - hw));
    }
}

// ---------------------------------------------------------------------------
// 3) big adjacency GEMM v8: BM=128 x BN, warp grid 2x4, split-K=4,
//    double-buffered cp.async B + pipelined bitmask A, hi/lo MMA batches.
// ---------------------------------------------------------------------------
template <int BN>
__global__ void __launch_bounds__(256, 2) big_gcn8() {
    constexpr int KSPLIT = 4;
    constexpr int BM  = 128;
    constexpr int KC  = 64;
    constexpr int NC  = (N / KSPLIT) / KC;   // 32 chunks
    constexpr int LDA = 72;
    constexpr int LDB = BN + 8;
    constexpr int ASZ = BM * LDA;
    constexpr int BSZ = KC * LDB;
    constexpr int WN  = BN / 4;
    constexpr int FM  = 4;
    constexpr int FN  = WN / 16;
    constexpr int SEG = BN / 8;
    constexpr int CPB = KC * SEG / 256;

    extern __shared__ __align__(16) __nv_bfloat16 smem[];
    __nv_bfloat16* sA  = smem;
    __nv_bfloat16* sBh = smem + 2 * ASZ;
    __nv_bfloat16* sBl = smem + 2 * ASZ + 2 * BSZ;

    int tid  = threadIdx.x;
    int warp = tid >> 5;
    int wr   = warp >> 2;
    int wc   = warp & 3;
    int r0   = blockIdx.x * BM;
    int ks0  = blockIdx.z * (N / KSPLIT);

    int arow = tid >> 1;
    const uint32_t* wptr = &g_bits[(size_t)(r0 + arow) * WORDS + (ks0 >> 5) + (tid & 1)];
    uint32_t abase = (uint32_t)__cvta_generic_to_shared(&sA[arow * LDA + (tid & 1) * 32]);

    wmma::fragment<wmma::accumulator, 16, 16, 16, float> acc[FM][FN];
#pragma unroll
    for (int fm = 0; fm < FM; ++fm)
#pragma unroll
        for (int fn = 0; fn < FN; ++fn) wmma::fill_fragment(acc[fm][fn], 0.f);

    auto fetchB = [&](int ch, int buf) {
        int k0 = ks0 + ch * KC;
#pragma unroll
        for (int i = 0; i < CPB; ++i) {
            int s = tid + i * 256;
            int row = s / SEG, seg = s % SEG;
            size_t g = (size_t)(k0 + row) * BN + seg * 8;
            cp16(&sBh[buf * BSZ + row * LDB + seg * 8], &g_ydh[g]);
            cp16(&sBl[buf * BSZ + row * LDB + seg * 8], &g_ydl[g]);
        }
        cp_commit();
    };
    auto storeA = [&](uint32_t w, int buf) {
        uint32_t base = abase + buf * (ASZ * 2);
#pragma unroll
        for (int j = 0; j < 4; ++j) {
            uint32_t bb = w >> (j * 8);
            uint4 u;
            u.x = ((bb & 1u)  ? 0x3F80u : 0u) | ((bb & 2u)   ? 0x3F800000u : 0u);
            u.y = ((bb & 4u)  ? 0x3F80u : 0u) | ((bb & 8u)   ? 0x3F800000u : 0u);
            u.z = ((bb & 16u) ? 0x3F80u : 0u) | ((bb & 32u)  ? 0x3F800000u : 0u);
            u.w = ((bb & 64u) ? 0x3F80u : 0u) | ((bb & 128u) ? 0x3F800000u : 0u);
            asm volatile("st.shared.v4.b32 [%0], {%1, %2, %3, %4};"
                         :: "r"(base + j * 16), "r"(u.x), "r"(u.y), "r"(u.z), "r"(u.w));
        }
    };

    fetchB(0, 0);
    storeA(wptr[0], 0);
    cp_wait0();
    __syncthreads();

    int buf = 0;
    for (int ch = 0; ch < NC; ++ch) {
        int nbuf = buf ^ 1;
        uint32_t wnext = 0;
        if (ch + 1 < NC) {
            fetchB(ch + 1, nbuf);
            wnext = wptr[(ch + 1) * 2];
        }
#pragma unroll
        for (int ks = 0; ks < 4; ++ks) {
            wmma::fragment<wmma::matrix_a, 16, 16, 16, __nv_bfloat16, wmma::row_major> a[FM];
#pragma unroll
            for (int fm = 0; fm < FM; ++fm)
                wmma::load_matrix_sync(a[fm],
                    &sA[buf * ASZ + (wr * 64 + fm * 16) * LDA + ks * 16], LDA);
#pragma unroll
            for (int fn = 0; fn < FN; ++fn) {
                wmma::fragment<wmma::matrix_b, 16, 16, 16, __nv_bfloat16, wmma::row_major> bh, bl;
                int bcol = wc * WN + fn * 16;
                wmma::load_matrix_sync(bh, &sBh[buf * BSZ + (ks * 16) * LDB + bcol], LDB);
                wmma::load_matrix_sync(bl, &sBl[buf * BSZ + (ks * 16) * LDB + bcol], LDB);
                // all-hi batch, then all-lo batch: 4 independent MMAs back-to-back
#pragma unroll
                for (int fm = 0; fm < FM; ++fm)
                    wmma::mma_sync(acc[fm][fn], a[fm], bh, acc[fm][fn]);
#pragma unroll
                for (int fm = 0; fm < FM; ++fm)
                    wmma::mma_sync(acc[fm][fn], a[fm], bl, acc[fm][fn]);
            }
        }
        if (ch + 1 < NC) {
            storeA(wnext, nbuf);
            cp_wait0();
        }
        __syncthreads();
        buf = nbuf;
    }

    float* pout = &g_part[(size_t)blockIdx.z * N * BN];
#pragma unroll
    for (int fm = 0; fm < FM; ++fm)
#pragma unroll
        for (int fn = 0; fn < FN; ++fn)
            wmma::store_matrix_sync(
                &pout[(size_t)(r0 + wr * 64 + fm * 16) * BN + wc * WN + fn * 16],
                acc[fm][fn], BN, wmma::mem_row_major);
}

constexpr int SMEM_BG8_128 = (2 * 128 * 72 + 4 * 64 * 136) * 2;  // 106496 B
constexpr int SMEM_BG8_64  = (2 * 128 * 72 + 4 * 64 * 72) * 2;   //  73728 B

// ---------------------------------------------------------------------------
// 3b) combine: out = lrelu(dinv_i*(sum_p part_p + yd_i) + bias)
// ---------------------------------------------------------------------------
__global__ void __launch_bounds__(256) combine_kernel(const float* __restrict__ bias_a,
                                                      const float* __restrict__ bias_b,
                                                      int bsplit, int C,
                                                      float* out_ext, int dest_sel,
                                                      int out_ld) {
    float* out = (dest_sel == 0) ? g_h : ((dest_sel == 1) ? g_rexd : out_ext);
    int i = blockIdx.x * 256 + threadIdx.x;
    int cq = C >> 2;
    int row = i / cq;
    int c4  = (i - row * cq) * 4;
    float di = g_dinv[row];
    size_t o = (size_t)row * C + c4;
    float4 s = *(const float4*)&g_ydf[o];
#pragma unroll
    for (int p = 0; p < 4; ++p) {
        float4 pp = *(const float4*)&g_part[(size_t)p * N * C + o];
        s.x += pp.x; s.y += pp.y; s.z += pp.z; s.w += pp.w;
    }
    const float* bias = (c4 < bsplit) ? bias_a : bias_b;
    int bo = (c4 < bsplit) ? c4 : c4 - bsplit;
    float4 v;
    v.x = di * s.x + bias[bo + 0];
    v.y = di * s.y + bias[bo + 1];
    v.z = di * s.z + bias[bo + 2];
    v.w = di * s.w + bias[bo + 3];
    v.x = (v.x > 0.f) ? v.x : 0.01f * v.x;
    v.y = (v.y > 0.f) ? v.y : 0.01f * v.y;
    v.z = (v.z > 0.f) ? v.z : 0.01f * v.z;
    v.w = (v.w > 0.f) ? v.w : 0.01f * v.w;
    *(float4*)&out[(size_t)row * out_ld + c4] = v;
}

// ---------------------------------------------------------------------------
// 4) split re into hi/lo
// ---------------------------------------------------------------------------
__global__ void split_re_kernel() {
    int i = blockIdx.x * blockDim.x + threadIdx.x;
    int r = i >> 6, c = i & 63;
    float v = g_rexd[r * 128 + c];
    __nv_bfloat16 hi = __float2bfloat16(v);
    g_reh[i] = hi;
    g_rel[i] = __float2bfloat16(v - __bfloat162float(hi));
}

// ---------------------------------------------------------------------------
// 5) recon = sigmoid(re @ re^T), symmetric, 128x128 tiles
// ---------------------------------------------------------------------------
__device__ __forceinline__ float fsig(float x) {
    return __fdividef(1.f, 1.f + __expf(-x));
}

constexpr int RLD  = 72;   // staging ld (elems)
constexpr int RLDC = 132;  // sC ld (floats)
constexpr int SMEM_RECON = 4 * 128 * RLD * 2;  // 73728 B (sC 67584 aliases)

__global__ void __launch_bounds__(256, 2) recon_kernel(float* __restrict__ out) {
    if (blockIdx.x < blockIdx.y) return;

    extern __shared__ __align__(16) __nv_bfloat16 smem[];
    __nv_bfloat16* sAh = smem;
    __nv_bfloat16* sAl = smem + 1 * 128 * RLD;
    __nv_bfloat16* sBh = smem + 2 * 128 * RLD;
    __nv_bfloat16* sBl = smem + 3 * 128 * RLD;

    int tid = threadIdx.x;
    int r0 = blockIdx.y * 128, c0 = blockIdx.x * 128;

    // stage: 128 rows x 64 cols per matrix; thread -> (row=tid>>1, half=(tid&1)*32)
    int srow = tid >> 1;
    int soff = (tid & 1) * 32;
    {
        const uint4* s;
        uint4* d;
        s = (const uint4*)&g_reh[(size_t)(r0 + srow) * 64 + soff];
        d = (uint4*)&sAh[srow * RLD + soff];
        d[0] = s[0]; d[1] = s[1]; d[2] = s[2]; d[3] = s[3];
        s = (const uint4*)&g_rel[(size_t)(r0 + srow) * 64 + soff];
        d = (uint4*)&sAl[srow * RLD + soff];
        d[0] = s[0]; d[1] = s[1]; d[2] = s[2]; d[3] = s[3];
        s = (const uint4*)&g_reh[(size_t)(c0 + srow) * 64 + soff];
        d = (uint4*)&sBh[srow * RLD + soff];
        d[0] = s[0]; d[1] = s[1]; d[2] = s[2]; d[3] = s[3];
        s = (const uint4*)&g_rel[(size_t)(c0 + srow) * 64 + soff];
        d = (uint4*)&sBl[srow * RLD + soff];
        d[0] = s[0]; d[1] = s[1]; d[2] = s[2]; d[3] = s[3];
    }
    __syncthreads();

    int warp = tid >> 5;
    int lane = tid & 31;
    int wr = warp >> 2;   // 0..1  (rows: wr*64)
    int wc = warp & 3;    // 0..3  (cols: wc*32)

    wmma::fragment<wmma::accumulator, 16, 16, 16, float> acc[4][2];
#pragma unroll
    for (int fm = 0; fm < 4; ++fm)
#pragma unroll
        for (int fn = 0; fn < 2; ++fn) wmma::fill_fragment(acc[fm][fn], 0.f);

#pragma unroll
    for (int ks = 0; ks < 4; ++ks) {
        int k = ks * 16;
        wmma::fragment<wmma::matrix_a, 16, 16, 16, __nv_bfloat16, wmma::row_major> ah[4], al[4];
#pragma unroll
        for (int fm = 0; fm < 4; ++fm) {
            wmma::load_matrix_sync(ah[fm], &sAh[(wr * 64 + fm * 16) * RLD + k], RLD);
            wmma::load_matrix_sync(al[fm], &sAl[(wr * 64 + fm * 16) * RLD + k], RLD);
        }
#pragma unroll
        for (int fn = 0; fn < 2; ++fn) {
            int col = wc * 32 + fn * 16;
            wmma::fragment<wmma::matrix_b, 16, 16, 16, __nv_bfloat16, wmma::col_major> bh, bl;
            wmma::load_matrix_sync(bh, &sBh[col * RLD + k], RLD);
            wmma::load_matrix_sync(bl, &sBl[col * RLD + k], RLD);
#pragma unroll
            for (int fm = 0; fm < 4; ++fm)
                wmma::mma_sync(acc[fm][fn], ah[fm], bh, acc[fm][fn]);
#pragma unroll
            for (int fm = 0; fm < 4; ++fm)
                wmma::mma_sync(acc[fm][fn], ah[fm], bl, acc[fm][fn]);
#pragma unroll
            for (int fm = 0; fm < 4; ++fm)
                wmma::mma_sync(acc[fm][fn], al[fm], bh, acc[fm][fn]);
        }
    }
    __syncthreads();  // staging buffers dead; sC aliases them

    float* sC = reinterpret_cast<float*>(smem);  // 128 x RLDC
#pragma unroll
    for (int fm = 0; fm < 4; ++fm)
#pragma unroll
        for (int fn = 0; fn < 2; ++fn)
            wmma::store_matrix_sync(&sC[(wr * 64 + fm * 16) * RLDC + wc * 32 + fn * 16],
                                    acc[fm][fn], RLDC, wmma::mem_row_major);
    __syncthreads();

    // direct tile: 128 rows x 32 float4
#pragma unroll
    for (int it = 0; it < 16; ++it) {
        int f4 = tid + it * 256;
        int r  = f4 >> 5;
        int c4 = (f4 & 31) << 2;
        float4 o;
        o.x = fsig(sC[r * RLDC + c4 + 0]);
        o.y = fsig(sC[r * RLDC + c4 + 1]);
        o.z = fsig(sC[r * RLDC + c4 + 2]);
        o.w = fsig(sC[r * RLDC + c4 + 3]);
        *(float4*)&out[(size_t)(r0 + r) * N + c0 + c4] = o;
    }
    // transposed tile: lane-major (coalesced STG.32)
    if (blockIdx.x != blockIdx.y) {
#pragma unroll
        for (int i = 0; i < 16; ++i) {
            int c = warp * 16 + i;  // sC column -> transposed row
#pragma unroll
            for (int q = 0; q < 4; ++q) {
                float v = sC[c * RLDC + q * 32 + lane];
                out[(size_t)(c0 + c) * N + r0 + q * 32 + lane] = fsig(v);
            }
        }
    }
}

// ---------------------------------------------------------------------------
// Launch chain (4th launch = big_gcn8<64> -> profiled)
// ---------------------------------------------------------------------------
extern "C" void kernel_launch(void* const* d_in, const int* in_sizes, int n_in,
                              void* d_out, int out_size) {
    (void)in_sizes; (void)n_in; (void)out_size;
    const float* x    = (const float*)d_in[0];
    const int*   edge = (const int*)  d_in[1];
    const float* W1   = (const float*)d_in[2];
    const float* b1   = (const float*)d_in[3];
    const float* W2   = (const float*)d_in[4];
    const float* b2   = (const float*)d_in[5];
    const float* We   = (const float*)d_in[6];
    const float* be   = (const float*)d_in[7];
    const float* Wd1  = (const float*)d_in[8];
    const float* bd1  = (const float*)d_in[9];
    const float* Wd2  = (const float*)d_in[10];
    const float* bd2  = (const float*)d_in[11];

    float* out   = (float*)d_out;
    float* recon = out;
    float* xout  = out + (size_t)N * N;
    float* zout  = xout + (size_t)N * 128;

    cudaFuncSetAttribute(big_gcn8<128>, cudaFuncAttributeMaxDynamicSharedMemorySize, SMEM_BG8_128);
    cudaFuncSetAttribute(big_gcn8<64>,  cudaFuncAttributeMaxDynamicSharedMemorySize, SMEM_BG8_64);
    cudaFuncSetAttribute(recon_kernel,  cudaFuncAttributeMaxDynamicSharedMemorySize, SMEM_RECON);

    prep_kernel<<<N, 256>>>(edge);                                            // 1
    small_gemm5<128, 64><<<512, 256>>>(x, 0, 128, 0, W1, nullptr, 64, 0);     // 2
    noop_kernel<<<1, 32>>>();                                                 // 3

    // layer 1: h = lrelu(nadj @ (x@W1) + b1)   [N,64]
    big_gcn8<64><<<dim3(64, 1, 4), 256, SMEM_BG8_64>>>();                     // 4 <- profiled
    combine_kernel<<<N * 64 / 1024, 256>>>(b1, b1, 64, 64, nullptr, 0, 64);   // 5

    // layer 2: z = lrelu(nadj @ (h@W2) + b2)   [N,128]
    small_gemm5<64, 128><<<512, 256>>>(nullptr, 1, 64, 0, W2, nullptr, 128, 0);    // 6
    big_gcn8<128><<<dim3(64, 1, 4), 256, SMEM_BG8_128>>>();                        // 7
    combine_kernel<<<N * 128 / 1024, 256>>>(b2, b2, 128, 128, zout, 2, 128);       // 8

    // layers 3+4 fused: [re | xd] = lrelu(nadj @ (z@[We|Wd1]) + [be|bd1])
    small_gemm5<128, 128><<<512, 256>>>(zout, 0, 128, 0, We, Wd1, 128, 0);         // 9
    big_gcn8<128><<<dim3(64, 1, 4), 256, SMEM_BG8_128>>>();                        // 10
    combine_kernel<<<N * 128 / 1024, 256>>>(be, bd1, 64, 128, nullptr, 1, 128);    // 11

    split_re_kernel<<<(N * 64) / 256, 256>>>();                                    // 12

    // layer 5: x_out = lrelu(nadj @ (xd@Wd2) + bd2)  [N,128]
    small_gemm5<64, 128><<<512, 256>>>(nullptr, 2, 128, 64, Wd2, nullptr, 128, 0); // 13
    big_gcn8<128><<<dim3(64, 1, 4), 256, SMEM_BG8_128>>>();                        // 14
    combine_kernel<<<N * 128 / 1024, 256>>>(bd2, bd2, 128, 128, xout, 2, 128);     // 15

    // recon = sigmoid(re @ re^T)  128x128 tiles, upper triangle
    recon_kernel<<<dim3(64, 64), 256, SMEM_RECON>>>(recon);                        // 16
}

// round 10
// speedup vs baseline: 2.5249x; 1.5425x over previous
#include <cuda_runtime.h>
#include <cuda_fp16.h>
#include <mma.h>
#include <stdint.h>

using namespace nvcuda;

constexpr int N     = 8192;
constexpr int WORDS = N / 32;

// ---------------------------------------------------------------------------
// Scratch
// ---------------------------------------------------------------------------
__device__ uint32_t       g_bits[(size_t)N * WORDS];   // 8 MB adjacency bitmask
__device__ float          g_dinv[N];
__device__ unsigned int   g_absmax[4];                 // per-layer max|yd| (fp32 bits)
__device__ float          g_ydf[(size_t)N * 128];      // dinv_j * (Y@W) fp32
__device__ __half         g_ydh[(size_t)N * 128];      // fp16 operand, scaled to normal range
__device__ float          g_part[4 * (size_t)N * 128]; // split-K partials (fp32)
__device__ float          g_h[(size_t)N * 64];
__device__ float          g_rexd[(size_t)N * 128];     // [re | xd]
__device__ __half         g_reh[(size_t)N * 64];       // re * 64 (fp16)

// ---------------------------------------------------------------------------
// helpers
// ---------------------------------------------------------------------------
__device__ __forceinline__ void cp16(void* smem_dst, const void* gsrc) {
    uint32_t d = (uint32_t)__cvta_generic_to_shared(smem_dst);
    asm volatile("cp.async.cg.shared.global [%0], [%1], 16;\n" :: "r"(d), "l"(gsrc));
}
__device__ __forceinline__ void cp_commit() {
    asm volatile("cp.async.commit_group;\n" ::: "memory");
}
__device__ __forceinline__ void cp_wait0() {
    asm volatile("cp.async.wait_group 0;\n" ::: "memory");
}
__device__ __forceinline__ float layer_scale(int slot) {       // yd -> fp16 scale
    float m = __uint_as_float(g_absmax[slot]);
    int e; frexpf(m, &e);
    return ldexpf(1.f, 11 - e);        // max*s in [2^10, 2^11)
}
__device__ __forceinline__ float layer_inv_scale(int slot) {
    float m = __uint_as_float(g_absmax[slot]);
    int e; frexpf(m, &e);
    return ldexpf(1.f, e - 11);
}

// ---------------------------------------------------------------------------
// 1) Prep: bitmask + dinv (+ absmax reset)
// ---------------------------------------------------------------------------
__global__ void __launch_bounds__(256) prep_kernel(const int* __restrict__ edge) {
    int row  = blockIdx.x;
    int lane = threadIdx.x & 31;
    int warp = threadIdx.x >> 5;
    __shared__ int wcnt[8];

    if (blockIdx.x == 0 && threadIdx.x < 4) g_absmax[threadIdx.x] = 0u;

    const int* erow = edge + (size_t)row * N;
    int cnt = 0;
#pragma unroll 4
    for (int w = 0; w < 32; ++w) {
        int col = warp * 1024 + w * 32 + lane;
        unsigned mask = __ballot_sync(0xFFFFFFFFu, erow[col] != 0);
        if (lane == 0) {
            g_bits[(size_t)row * WORDS + warp * 32 + w] = mask;
            cnt += __popc(mask);
        }
    }
    if (lane == 0) wcnt[warp] = cnt;
    __syncthreads();
    if (threadIdx.x == 0) {
        int deg = 1;
#pragma unroll
        for (int i = 0; i < 8; ++i) deg += wcnt[i];
        g_dinv[row] = rsqrtf((float)deg);
    }
}

// ---------------------------------------------------------------------------
// 2) small GEMM: yd = dinv_r * (act @ W) -> ydf (fp32) + absmax[slot]
// ---------------------------------------------------------------------------
template <int KIN, int COUT>
__global__ void __launch_bounds__(256) small_gemm7(const float* __restrict__ act_ext,
                                                   int act_sel, int act_ld, int act_c0,
                                                   const float* __restrict__ Wa,
                                                   const float* __restrict__ Wb,
                                                   int out_ld, int out_c0, int slot) {
    const float* act = (act_sel == 1) ? g_h : ((act_sel == 2) ? g_rexd : act_ext);
    __shared__ float sW[KIN * COUT];
    __shared__ float sact[16 * KIN];
    __shared__ unsigned int samax;

    int tid = threadIdx.x;
    if (tid == 0) samax = 0u;
    if (Wb == nullptr) {
        for (int i = tid; i < KIN * COUT; i += 256) sW[i] = Wa[i];
    } else {
        for (int i = tid; i < KIN * COUT; i += 256) {
            int k = i / COUT, c = i % COUT;
            sW[i] = (c < 64) ? Wa[k * 64 + c] : Wb[k * 64 + (c - 64)];
        }
    }

    int rbase = blockIdx.x * 16;
    for (int j = tid; j < 16 * KIN; j += 256) {
        int r = j / KIN, k = j - r * KIN;
        sact[j] = act[(size_t)(rbase + r) * act_ld + act_c0 + k];
    }
    __syncthreads();

    constexpr int TPR = COUT / 4;
    constexpr int RPI = 256 / TPR;

    int c4 = (tid % TPR) * 4;
    int ry0 = tid / TPR;
    float amax = 0.f;

#pragma unroll
    for (int it = 0; it < 16; it += RPI) {
        int ry = it + ry0;
        const float* sa = &sact[ry * KIN];
        float4 a0 = make_float4(0.f, 0.f, 0.f, 0.f);
        float4 a1 = make_float4(0.f, 0.f, 0.f, 0.f);
#pragma unroll
        for (int k = 0; k < KIN; k += 2) {
            float v0 = sa[k], v1 = sa[k + 1];
            float4 w0 = *(const float4*)&sW[k * COUT + c4];
            float4 w1 = *(const float4*)&sW[(k + 1) * COUT + c4];
            a0.x = fmaf(v0, w0.x, a0.x); a0.y = fmaf(v0, w0.y, a0.y);
            a0.z = fmaf(v0, w0.z, a0.z); a0.w = fmaf(v0, w0.w, a0.w);
            a1.x = fmaf(v1, w1.x, a1.x); a1.y = fmaf(v1, w1.y, a1.y);
            a1.z = fmaf(v1, w1.z, a1.z); a1.w = fmaf(v1, w1.w, a1.w);
        }
        int row = rbase + ry;
        float di = g_dinv[row];
        float4 y;
        y.x = di * (a0.x + a1.x); y.y = di * (a0.y + a1.y);
        y.z = di * (a0.z + a1.z); y.w = di * (a0.w + a1.w);
        *(float4*)&g_ydf[(size_t)row * out_ld + out_c0 + c4] = y;
        amax = fmaxf(amax, fmaxf(fmaxf(fabsf(y.x), fabsf(y.y)),
                                 fmaxf(fabsf(y.z), fabsf(y.w))));
    }
    atomicMax(&samax, __float_as_uint(amax));
    __syncthreads();
    if (tid == 0) atomicMax(&g_absmax[slot], samax);
}

// ---------------------------------------------------------------------------
// 2b) convert: ydh = fp16(ydf * scale[slot])
// ---------------------------------------------------------------------------
__global__ void __launch_bounds__(256) convert_kernel(int slot) {
    float s = layer_scale(slot);
    size_t i = ((size_t)blockIdx.x * 256 + threadIdx.x) * 4;
    float4 y = *(const float4*)&g_ydf[i];
    __half2 p01 = __floats2half2_rn(y.x * s, y.y * s);
    __half2 p23 = __floats2half2_rn(y.z * s, y.w * s);
    *(uint2*)&g_ydh[i] = make_uint2(*(uint32_t*)&p01, *(uint32_t*)&p23);
}

// ---------------------------------------------------------------------------
// 3) big adjacency GEMM (fp16 single): BM=128 x BN, warp grid 2x4, split-K=4
// ---------------------------------------------------------------------------
template <int BN, int MAXCTA>
__global__ void __launch_bounds__(256, MAXCTA) big_gcn9() {
    constexpr int KSPLIT = 4;
    constexpr int BM  = 128;
    constexpr int KC  = 64;
    constexpr int NC  = (N / KSPLIT) / KC;
    constexpr int LDA = 72;
    constexpr int LDB = BN + 8;
    constexpr int ASZ = BM * LDA;
    constexpr int BSZ = KC * LDB;
    constexpr int WN  = BN / 4;
    constexpr int FM  = 4;
    constexpr int FN  = WN / 16;
    constexpr int SEG = BN / 8;
    constexpr int CPB = KC * SEG / 256;

    extern __shared__ __align__(16) __half smem[];
    __half* sA = smem;
    __half* sB = smem + 2 * ASZ;

    int tid  = threadIdx.x;
    int warp = tid >> 5;
    int wr   = warp >> 2;
    int wc   = warp & 3;
    int r0   = blockIdx.x * BM;
    int ks0  = blockIdx.z * (N / KSPLIT);

    int arow = tid >> 1;
    const uint32_t* wptr = &g_bits[(size_t)(r0 + arow) * WORDS + (ks0 >> 5) + (tid & 1)];
    uint32_t abase = (uint32_t)__cvta_generic_to_shared(&sA[arow * LDA + (tid & 1) * 32]);

    wmma::fragment<wmma::accumulator, 16, 16, 16, float> acc[FM][FN];
#pragma unroll
    for (int fm = 0; fm < FM; ++fm)
#pragma unroll
        for (int fn = 0; fn < FN; ++fn) wmma::fill_fragment(acc[fm][fn], 0.f);

    auto fetchB = [&](int ch, int buf) {
        int k0 = ks0 + ch * KC;
#pragma unroll
        for (int i = 0; i < CPB; ++i) {
            int s = tid + i * 256;
            int row = s / SEG, seg = s % SEG;
            cp16(&sB[buf * BSZ + row * LDB + seg * 8],
                 &g_ydh[(size_t)(k0 + row) * BN + seg * 8]);
        }
        cp_commit();
    };
    auto storeA = [&](uint32_t w, int buf) {
        uint32_t base = abase + buf * (ASZ * 2);
#pragma unroll
        for (int j = 0; j < 4; ++j) {
            uint32_t bb = w >> (j * 8);
            uint4 u;
            u.x = ((bb & 1u)  ? 0x3C00u : 0u) | ((bb & 2u)   ? 0x3C000000u : 0u);
            u.y = ((bb & 4u)  ? 0x3C00u : 0u) | ((bb & 8u)   ? 0x3C000000u : 0u);
            u.z = ((bb & 16u) ? 0x3C00u : 0u) | ((bb & 32u)  ? 0x3C000000u : 0u);
            u.w = ((bb & 64u) ? 0x3C00u : 0u) | ((bb & 128u) ? 0x3C000000u : 0u);
            asm volatile("st.shared.v4.b32 [%0], {%1, %2, %3, %4};"
                         :: "r"(base + j * 16), "r"(u.x), "r"(u.y), "r"(u.z), "r"(u.w));
        }
    };

    fetchB(0, 0);
    storeA(wptr[0], 0);
    cp_wait0();
    __syncthreads();

    int buf = 0;
    for (int ch = 0; ch < NC; ++ch) {
        int nbuf = buf ^ 1;
        uint32_t wnext = 0;
        if (ch + 1 < NC) {
            fetchB(ch + 1, nbuf);
            wnext = wptr[(ch + 1) * 2];
        }
#pragma unroll
        for (int ks = 0; ks < 4; ++ks) {
            wmma::fragment<wmma::matrix_a, 16, 16, 16, __half, wmma::row_major> a[FM];
#pragma unroll
            for (int fm = 0; fm < FM; ++fm)
                wmma::load_matrix_sync(a[fm],
                    &sA[buf * ASZ + (wr * 64 + fm * 16) * LDA + ks * 16], LDA);
#pragma unroll
            for (int fn = 0; fn < FN; ++fn) {
                wmma::fragment<wmma::matrix_b, 16, 16, 16, __half, wmma::row_major> b;
                int bcol = wc * WN + fn * 16;
                wmma::load_matrix_sync(b, &sB[buf * BSZ + (ks * 16) * LDB + bcol], LDB);
#pragma unroll
                for (int fm = 0; fm < FM; ++fm)
                    wmma::mma_sync(acc[fm][fn], a[fm], b, acc[fm][fn]);
            }
        }
        if (ch + 1 < NC) {
            storeA(wnext, nbuf);
            cp_wait0();
        }
        __syncthreads();
        buf = nbuf;
    }

    float* pout = &g_part[(size_t)blockIdx.z * N * BN];
#pragma unroll
    for (int fm = 0; fm < FM; ++fm)
#pragma unroll
        for (int fn = 0; fn < FN; ++fn)
            wmma::store_matrix_sync(
                &pout[(size_t)(r0 + wr * 64 + fm * 16) * BN + wc * WN + fn * 16],
                acc[fm][fn], BN, wmma::mem_row_major);
}

constexpr int SMEM_BG9_128 = (2 * 128 * 72 + 2 * 64 * 136) * 2;  // 71680 B
constexpr int SMEM_BG9_64  = (2 * 128 * 72 + 2 * 64 * 72) * 2;   // 55296 B

// ---------------------------------------------------------------------------
// 3b) combine: out = lrelu(dinv_i*(inv_s * sum_p part_p + yd_i) + bias)
// ---------------------------------------------------------------------------
__global__ void __launch_bounds__(256) combine_kernel(const float* __restrict__ bias_a,
                                                      const float* __restrict__ bias_b,
                                                      int bsplit, int C, int slot,
                                                      float* out_ext, int dest_sel,
                                                      int out_ld) {
    float* out = (dest_sel == 0) ? g_h : ((dest_sel == 1) ? g_rexd : out_ext);
    float inv = layer_inv_scale(slot);
    int i = blockIdx.x * 256 + threadIdx.x;
    int cq = C >> 2;
    int row = i / cq;
    int c4  = (i - row * cq) * 4;
    float di = g_dinv[row];
    size_t o = (size_t)row * C + c4;
    float4 p = make_float4(0.f, 0.f, 0.f, 0.f);
#pragma unroll
    for (int pz = 0; pz < 4; ++pz) {
        float4 pp = *(const float4*)&g_part[(size_t)pz * N * C + o];
        p.x += pp.x; p.y += pp.y; p.z += pp.z; p.w += pp.w;
    }
    float4 yd = *(const float4*)&g_ydf[o];
    const float* bias = (c4 < bsplit) ? bias_a : bias_b;
    int bo = (c4 < bsplit) ? c4 : c4 - bsplit;
    float4 v;
    v.x = di * (p.x * inv + yd.x) + bias[bo + 0];
    v.y = di * (p.y * inv + yd.y) + bias[bo + 1];
    v.z = di * (p.z * inv + yd.z) + bias[bo + 2];
    v.w = di * (p.w * inv + yd.w) + bias[bo + 3];
    v.x = (v.x > 0.f) ? v.x : 0.01f * v.x;
    v.y = (v.y > 0.f) ? v.y : 0.01f * v.y;
    v.z = (v.z > 0.f) ? v.z : 0.01f * v.z;
    v.w = (v.w > 0.f) ? v.w : 0.01f * v.w;
    *(float4*)&out[(size_t)row * out_ld + c4] = v;
}

// ---------------------------------------------------------------------------
// 4) split re: fp16, fixed x64 scale
// ---------------------------------------------------------------------------
__global__ void split_re_kernel() {
    int i = blockIdx.x * blockDim.x + threadIdx.x;
    int r = i >> 6, c = i & 63;
    g_reh[i] = __float2half_rn(g_rexd[r * 128 + c] * 64.f);
}

// ---------------------------------------------------------------------------
// 5) recon = sigmoid((reh @ reh^T) / 4096), symmetric, 128x128 tiles, fp16
// ---------------------------------------------------------------------------
__device__ __forceinline__ float fsig(float x) {
    return __fdividef(1.f, 1.f + __expf(-x));
}

constexpr int RLD  = 72;
constexpr int RLDC = 132;
constexpr int SMEM_RECON = 128 * RLDC * 4;  // 67584 B (sC; > 2*128*RLD*2 staging)

__global__ void __launch_bounds__(256, 2) recon_kernel(float* __restrict__ out) {
    if (blockIdx.x < blockIdx.y) return;

    extern __shared__ __align__(16) __half smem2[];
    __half* sA = smem2;
    __half* sB = smem2 + 128 * RLD;

    int tid = threadIdx.x;
    int r0 = blockIdx.y * 128, c0 = blockIdx.x * 128;

    int srow = tid >> 1;
    int soff = (tid & 1) * 32;
    {
        const uint4* s;
        uint4* d;
        s = (const uint4*)&g_reh[(size_t)(r0 + srow) * 64 + soff];
        d = (uint4*)&sA[srow * RLD + soff];
        d[0] = s[0]; d[1] = s[1]; d[2] = s[2]; d[3] = s[3];
        s = (const uint4*)&g_reh[(size_t)(c0 + srow) * 64 + soff];
        d = (uint4*)&sB[srow * RLD + soff];
        d[0] = s[0]; d[1] = s[1]; d[2] = s[2]; d[3] = s[3];
    }
    __syncthreads();

    int warp = tid >> 5;
    int lane = tid & 31;
    int wr = warp >> 2;
    int wc = warp & 3;

    wmma::fragment<wmma::accumulator, 16, 16, 16, float> acc[4][2];
#pragma unroll
    for (int fm = 0; fm < 4; ++fm)
#pragma unroll
        for (int fn = 0; fn < 2; ++fn) wmma::fill_fragment(acc[fm][fn], 0.f);

#pragma unroll
    for (int ks = 0; ks < 4; ++ks) {
        int k = ks * 16;
        wmma::fragment<wmma::matrix_a, 16, 16, 16, __half, wmma::row_major> a[4];
#pragma unroll
        for (int fm = 0; fm < 4; ++fm)
            wmma::load_matrix_sync(a[fm], &sA[(wr * 64 + fm * 16) * RLD + k], RLD);
#pragma unroll
        for (int fn = 0; fn < 2; ++fn) {
            int col = wc * 32 + fn * 16;
            wmma::fragment<wmma::matrix_b, 16, 16, 16, __half, wmma::col_major> b;
            wmma::load_matrix_sync(b, &sB[col * RLD + k], RLD);
#pragma unroll
            for (int fm = 0; fm < 4; ++fm)
                wmma::mma_sync(acc[fm][fn], a[fm], b, acc[fm][fn]);
        }
    }
    __syncthreads();

    float* sC = reinterpret_cast<float*>(smem2);  // 128 x RLDC
#pragma unroll
    for (int fm = 0; fm < 4; ++fm)
#pragma unroll
        for (int fn = 0; fn < 2; ++fn)
            wmma::store_matrix_sync(&sC[(wr * 64 + fm * 16) * RLDC + wc * 32 + fn * 16],
                                    acc[fm][fn], RLDC, wmma::mem_row_major);
    __syncthreads();

    constexpr float INVS = 1.f / 4096.f;   // undo 64 * 64
#pragma unroll
    for (int it = 0; it < 16; ++it) {
        int f4 = tid + it * 256;
        int r  = f4 >> 5;
        int c4 = (f4 & 31) << 2;
        float4 o;
        o.x = fsig(sC[r * RLDC + c4 + 0] * INVS);
        o.y = fsig(sC[r * RLDC + c4 + 1] * INVS);
        o.z = fsig(sC[r * RLDC + c4 + 2] * INVS);
        o.w = fsig(sC[r * RLDC + c4 + 3] * INVS);
        *(float4*)&out[(size_t)(r0 + r) * N + c0 + c4] = o;
    }
    if (blockIdx.x != blockIdx.y) {
#pragma unroll
        for (int i = 0; i < 16; ++i) {
            int c = warp * 16 + i;
#pragma unroll
            for (int q = 0; q < 4; ++q) {
                float v = sC[c * RLDC + q * 32 + lane] * INVS;
                out[(size_t)(c0 + c) * N + r0 + q * 32 + lane] = fsig(v);
            }
        }
    }
}

// ---------------------------------------------------------------------------
// Launch chain (4th launch = big_gcn9<64,3> -> profiled)
// ---------------------------------------------------------------------------
extern "C" void kernel_launch(void* const* d_in, const int* in_sizes, int n_in,
                              void* d_out, int out_size) {
    (void)in_sizes; (void)n_in; (void)out_size;
    const float* x    = (const float*)d_in[0];
    const int*   edge = (const int*)  d_in[1];
    const float* W1   = (const float*)d_in[2];
    const float* b1   = (const float*)d_in[3];
    const float* W2   = (const float*)d_in[4];
    const float* b2   = (const float*)d_in[5];
    const float* We   = (const float*)d_in[6];
    const float* be   = (const float*)d_in[7];
    const float* Wd1  = (const float*)d_in[8];
    const float* bd1  = (const float*)d_in[9];
    const float* Wd2  = (const float*)d_in[10];
    const float* bd2  = (const float*)d_in[11];

    float* out   = (float*)d_out;
    float* recon = out;
    float* xout  = out + (size_t)N * N;
    float* zout  = xout + (size_t)N * 128;

    cudaFuncSetAttribute(big_gcn9<128, 2>, cudaFuncAttributeMaxDynamicSharedMemorySize, SMEM_BG9_128);
    cudaFuncSetAttribute(big_gcn9<64, 3>,  cudaFuncAttributeMaxDynamicSharedMemorySize, SMEM_BG9_64);
    cudaFuncSetAttribute(recon_kernel,     cudaFuncAttributeMaxDynamicSharedMemorySize, SMEM_RECON);

    prep_kernel<<<N, 256>>>(edge);                                              // 1

    // layer 1: h = lrelu(nadj @ (x@W1) + b1)   [N,64]
    small_gemm7<128, 64><<<512, 256>>>(x, 0, 128, 0, W1, nullptr, 64, 0, 0);    // 2
    convert_kernel<<<N * 64 / 1024, 256>>>(0);                                  // 3
    big_gcn9<64, 3><<<dim3(64, 1, 4), 256, SMEM_BG9_64>>>();                    // 4 <- profiled
    combine_kernel<<<N * 64 / 1024, 256>>>(b1, b1, 64, 64, 0, nullptr, 0, 64);  // 5

    // layer 2: z = lrelu(nadj @ (h@W2) + b2)   [N,128]
    small_gemm7<64, 128><<<512, 256>>>(nullptr, 1, 64, 0, W2, nullptr, 128, 0, 1);   // 6
    convert_kernel<<<N * 128 / 1024, 256>>>(1);                                      // 7
    big_gcn9<128, 2><<<dim3(64, 1, 4), 256, SMEM_BG9_128>>>();                       // 8
    combine_kernel<<<N * 128 / 1024, 256>>>(b2, b2, 128, 128, 1, zout, 2, 128);      // 9

    // layers 3+4 fused: [re | xd] = lrelu(nadj @ (z@[We|Wd1]) + [be|bd1])
    small_gemm7<128, 128><<<512, 256>>>(zout, 0, 128, 0, We, Wd1, 128, 0, 2);        // 10
    convert_kernel<<<N * 128 / 1024, 256>>>(2);                                      // 11
    big_gcn9<128, 2><<<dim3(64, 1, 4), 256, SMEM_BG9_128>>>();                       // 12
    combine_kernel<<<N * 128 / 1024, 256>>>(be, bd1, 64, 128, 2, nullptr, 1, 128);   // 13

    split_re_kernel<<<(N * 64) / 256, 256>>>();                                      // 14

    // layer 5: x_out = lrelu(nadj @ (xd@Wd2) + bd2)  [N,128]
    small_gemm7<64, 128><<<512, 256>>>(nullptr, 2, 128, 64, Wd2, nullptr, 128, 0, 3); // 15
    convert_kernel<<<N * 128 / 1024, 256>>>(3);                                       // 16
    big_gcn9<128, 2><<<dim3(64, 1, 4), 256, SMEM_BG9_128>>>();                        // 17
    combine_kernel<<<N * 128 / 1024, 256>>>(bd2, bd2, 128, 128, 3, xout, 2, 128);     // 18

    // recon = sigmoid(re @ re^T)  fp16, 128x128 tiles, upper triangle
    recon_kernel<<<dim3(64, 64), 256, SMEM_RECON>>>(recon);                           // 19
}